// round 12
// baseline (speedup 1.0000x reference)
#include <cuda_runtime.h>
#include <cuda_bf16.h>
#include <cstdint>
#include <math.h>

#define T_TOK 4096
#define H_DIM 2048
#define F_DIM 1024
#define E_NUM 16
#define K_TOP 4

#if defined(__CUDA_ARCH__) && (defined(__CUDA_ARCH_FEAT_SM103_ALL) || \
    defined(__CUDA_ARCH_FEAT_SM100_ALL) || defined(__CUDA_ARCH_SPECIFIC__) || \
    defined(__CUDA_ARCH_FAMILY_SPECIFIC__))
#define HAS_TCGEN05 1
#else
#define HAS_TCGEN05 0
#endif

// idesc kind::f16: dtype=F32(1<<4), atype=BF16(1<<7), btype=BF16(1<<10), (N/8)<<17, (M/16)<<24
#define IDESC_128x128 0x08200490u

#define SM_TMEMPTR 0
#define SM_MBARM   8
#define SM_FULL0   16
#define SM_FULL1   24
#define SM_STAGE0  1024
// combined hi|lo tiles: 16KB = 128 rows x [64B hi | 64B lo], K=32 per tile
#define STAGE_BYTES (3 * 16384)      // gu: A,Wg,Wu   dn: A0,A1,Wd
#define MMA_SMEM (1024 + 2 * STAGE_BYTES)   // 99328 -> 2 CTAs/SM, TMEM 2x256 = 512

// packed tile addressing (combined hi|lo 16KB tiles, pre-swizzled SW128)
#define PA_TILE(e, mt, kc)  (((((size_t)(e) * 32 + (mt)) * 64) + (kc)) << 14)   // K=2048: 64 chunks
#define WGU_TILE(e, ft, kc) (((((size_t)(e) * 8  + (ft)) * 64) + (kc)) << 14)   // K=2048: 64 chunks
#define WD_TILE(e, ht, kc)  (((((size_t)(e) * 16 + (ht)) * 32) + (kc)) << 14)   // K=1024: 32 chunks
#define ACT_TILE(e, mt, kc) (((((size_t)(e) * 32 + (mt)) * 32) + (kc)) << 14)   // K=1024: 32 chunks

// ---------------- device scratch ---------------------------------------------------
__device__ int   d_cnt[E_NUM];
__device__ int   d_tok[E_NUM * T_TOK];
__device__ int   d_slot[T_TOK * K_TOP];
__device__ float d_wk[T_TOK * K_TOP];
// packed (tile-contiguous, pre-swizzled, hi|lo combined) operands
__device__ __align__(128) char d_pa  [(size_t)E_NUM * T_TOK * H_DIM * 4];   // 512MB
__device__ __align__(128) char d_wgp [(size_t)E_NUM * F_DIM * H_DIM * 4];   // 128MB
__device__ __align__(128) char d_wup [(size_t)E_NUM * F_DIM * H_DIM * 4];   // 128MB
__device__ __align__(128) char d_wdp [(size_t)E_NUM * H_DIM * F_DIM * 4];   // 128MB
__device__ __align__(128) char d_actp[(size_t)E_NUM * T_TOK * F_DIM * 4];   // 256MB
__device__ float d_act_f32[(size_t)E_NUM * T_TOK * F_DIM];   // SIMT fallback path
__device__ float d_ybuf[(size_t)E_NUM * T_TOK * H_DIM];
__device__ float d_logits_fallback[(size_t)T_TOK * E_NUM];

// ---------------- portable PTX helpers ----------------------------------------------
__device__ __forceinline__ uint32_t elect_one_pred() {
    uint32_t pred;
    asm volatile("{\n\t.reg .pred p;\n\telect.sync _|p, 0xFFFFFFFF;\n\t"
                 "selp.b32 %0, 1, 0, p;\n\t}" : "=r"(pred));
    return pred;
}
__device__ __forceinline__ uint32_t smem_to_u32(const void* p) {
    uint32_t a;
    asm("{ .reg .u64 t; cvta.to.shared.u64 t, %1; cvt.u32.u64 %0, t; }" : "=r"(a) : "l"(p));
    return a;
}
__device__ __forceinline__ uint32_t swz(uint32_t off) { return off ^ ((off >> 3) & 0x70); }

#define MBARRIER_INIT(mbar, count) \
    asm volatile("mbarrier.init.shared.b64 [%0], %1;" :: "r"((uint32_t)(mbar)), "r"((uint32_t)(count)) : "memory")
#define MBARRIER_INVAL(mbar) \
    asm volatile("mbarrier.inval.shared.b64 [%0];" :: "r"((uint32_t)(mbar)) : "memory")
#define MBARRIER_EXPECT_TX(mbar, bytes) \
    asm volatile("mbarrier.arrive.expect_tx.shared.b64 _, [%0], %1;" :: "r"((uint32_t)(mbar)), "r"((uint32_t)(bytes)) : "memory")

#define MBARRIER_WAIT_PARITY(mbar_smem_addr, phase_parity) do { \
    uint32_t _mbar = (uint32_t)(mbar_smem_addr); \
    uint32_t _parity = (uint32_t)(phase_parity); \
    uint32_t _done; \
    asm volatile("{\n\t.reg .pred p;\n\t" \
        "mbarrier.try_wait.parity.acquire.cta.shared::cta.b64 p, [%1], %2;\n\t" \
        "selp.b32 %0, 1, 0, p;\n\t}" \
        : "=r"(_done) : "r"(_mbar), "r"(_parity) : "memory"); \
    if (!_done) { \
        asm volatile("{\n\t.reg .pred P1;\n\t" \
            "WAIT_LOOP_%=:\n\t" \
            "mbarrier.try_wait.parity.acquire.cta.shared::cta.b64 P1, [%0], %1, 0x989680;\n\t" \
            "@P1 bra.uni WAIT_DONE_%=;\n\t" \
            "bra.uni WAIT_LOOP_%=;\n\t" \
            "WAIT_DONE_%=:\n\t}" \
            :: "r"(_mbar), "r"(_parity) : "memory"); \
    } \
} while (0)

__device__ __forceinline__ uint32_t pack_bf16x2_hi(float f0, float f1) {
    __nv_bfloat162 h = __floats2bfloat162_rn(f0, f1);
    return *(uint32_t*)&h;
}
__device__ __forceinline__ uint32_t pack_bf16x2_lo(float f0, float f1) {
    __nv_bfloat16 h0 = __float2bfloat16(f0), h1 = __float2bfloat16(f1);
    __nv_bfloat162 l = __floats2bfloat162_rn(f0 - __bfloat162float(h0),
                                             f1 - __bfloat162float(h1));
    return *(uint32_t*)&l;
}

#if HAS_TCGEN05
#define TCGEN05_ALLOC(smem_addr, nCols) \
    asm volatile("tcgen05.alloc.cta_group::1.sync.aligned.shared::cta.b32 [%0], %1;" \
                 :: "r"((uint32_t)(smem_addr)), "r"((uint32_t)(nCols)) : "memory")
#define TCGEN05_RELINQ() \
    asm volatile("tcgen05.relinquish_alloc_permit.cta_group::1.sync.aligned;")
#define TCGEN05_DEALLOC(tmem, nCols) \
    asm volatile("tcgen05.dealloc.cta_group::1.sync.aligned.b32 %0, %1;" :: "r"(tmem), "r"((uint32_t)(nCols)))
#define TCGEN05_COMMIT(mbar) \
    asm volatile("tcgen05.commit.cta_group::1.mbarrier::arrive::one.shared::cluster.b64 [%0];" \
                 :: "r"((uint32_t)(mbar)) : "memory")
#define TCGEN05_FENCE_AFTER() asm volatile("tcgen05.fence::after_thread_sync;" ::: "memory")
#define TCGEN05_WAIT_LD()     asm volatile("tcgen05.wait::ld.sync.aligned;" ::: "memory")

#define TCGEN05_LD_32X32B_X32(r, tmem_addr) \
    asm volatile("tcgen05.ld.sync.aligned.32x32b.x32.b32 " \
        "{%0, %1, %2, %3, %4, %5, %6, %7, %8, %9, %10, %11, %12, %13, %14, %15, " \
        " %16, %17, %18, %19, %20, %21, %22, %23, %24, %25, %26, %27, %28, %29, %30, %31}, [%32];" \
        : "=r"((r)[0]),  "=r"((r)[1]),  "=r"((r)[2]),  "=r"((r)[3]), \
          "=r"((r)[4]),  "=r"((r)[5]),  "=r"((r)[6]),  "=r"((r)[7]), \
          "=r"((r)[8]),  "=r"((r)[9]),  "=r"((r)[10]), "=r"((r)[11]), \
          "=r"((r)[12]), "=r"((r)[13]), "=r"((r)[14]), "=r"((r)[15]), \
          "=r"((r)[16]), "=r"((r)[17]), "=r"((r)[18]), "=r"((r)[19]), \
          "=r"((r)[20]), "=r"((r)[21]), "=r"((r)[22]), "=r"((r)[23]), \
          "=r"((r)[24]), "=r"((r)[25]), "=r"((r)[26]), "=r"((r)[27]), \
          "=r"((r)[28]), "=r"((r)[29]), "=r"((r)[30]), "=r"((r)[31]) \
        : "r"(tmem_addr))

static constexpr uint64_t SMEM_DESC_BASE_SW128 =
    (uint64_t(2) << 61) | (uint64_t(1) << 46) | (uint64_t(64) << 32) | (uint64_t(1) << 16);
#define MAKE_SMEM_DESC(base_addr) (SMEM_DESC_BASE_SW128 | ((uint64_t)((base_addr) >> 4) & 0x3FFF))

__device__ __forceinline__ void mma_f16_ss(uint32_t d, uint64_t a, uint64_t b, bool acc) {
    uint32_t en = acc ? 1u : 0u;
    asm volatile("{\n\t.reg .pred p;\n\tsetp.ne.u32 p, %5, 0;\n\t"
                 "tcgen05.mma.cta_group::1.kind::f16 [%0], %1, %2, %3, {%4, %4, %4, %4}, p;\n\t}"
                 :: "r"(d), "l"(a), "l"(b), "r"(IDESC_128x128), "r"(0u), "r"(en) : "memory");
}

__device__ __forceinline__ void bulk_cp(uint32_t dst, const void* src, uint32_t bytes, uint32_t mbar) {
    asm volatile("cp.async.bulk.shared::cluster.global.mbarrier::complete_tx::bytes "
                 "[%0], [%1], %2, [%3];"
                 :: "r"(dst), "l"(src), "r"(bytes), "r"(mbar) : "memory");
}
#endif  // HAS_TCGEN05

// ---------------- init ---------------------------------------------------------------
__global__ void init_kernel() {
    if (threadIdx.x < E_NUM) d_cnt[threadIdx.x] = 0;
}

// ---------------- router (validated) ---------------------------------------------------
__global__ void __launch_bounds__(256) router_kernel(const float* __restrict__ x,
                                                     const float* __restrict__ wg,
                                                     float* __restrict__ logits_out) {
    int t = blockIdx.x, tid = threadIdx.x;
    float acc[E_NUM];
#pragma unroll
    for (int e = 0; e < E_NUM; e++) acc[e] = 0.f;
    const float* xr = x + (size_t)t * H_DIM;
    for (int h = tid; h < H_DIM; h += 256) {
        float xv = xr[h];
        const float* wrow = wg + (size_t)h * E_NUM;
#pragma unroll
        for (int e = 0; e < E_NUM; e++) acc[e] += xv * wrow[e];
    }
#pragma unroll
    for (int e = 0; e < E_NUM; e++) {
#pragma unroll
        for (int o = 16; o > 0; o >>= 1)
            acc[e] += __shfl_down_sync(0xffffffffu, acc[e], o);
    }
    __shared__ float sred[8][E_NUM];
    __shared__ float logits[E_NUM];
    int warp = tid >> 5, lane = tid & 31;
    if (lane == 0) {
#pragma unroll
        for (int e = 0; e < E_NUM; e++) sred[warp][e] = acc[e];
    }
    __syncthreads();
    if (tid < E_NUM) {
        float v = 0.f;
#pragma unroll
        for (int w = 0; w < 8; w++) v += sred[w][tid];
        logits[tid] = v;
        logits_out[(size_t)t * E_NUM + tid] = v;
    }
    __syncthreads();
    if (tid == 0) {
        float l[E_NUM];
#pragma unroll
        for (int e = 0; e < E_NUM; e++) l[e] = logits[e];
        int sel[K_TOP]; float selv[K_TOP]; bool used[E_NUM];
#pragma unroll
        for (int e = 0; e < E_NUM; e++) used[e] = false;
#pragma unroll
        for (int k = 0; k < K_TOP; k++) {
            int best = -1; float bv = -1e30f;
            for (int e = 0; e < E_NUM; e++)
                if (!used[e] && l[e] > bv) { bv = l[e]; best = e; }
            used[best] = true; sel[k] = best; selv[k] = bv;
        }
        float m = selv[0], w[K_TOP], sum = 0.f;
#pragma unroll
        for (int k = 0; k < K_TOP; k++) { w[k] = expf(selv[k] - m); sum += w[k]; }
        float inv = 1.f / sum;
#pragma unroll
        for (int k = 0; k < K_TOP; k++) {
            int e = sel[k];
            int pos = atomicAdd(&d_cnt[e], 1);
            d_tok[e * T_TOK + pos] = t;
            d_slot[t * K_TOP + k] = e * T_TOK + pos;
            d_wk[t * K_TOP + k] = w[k] * inv;
        }
    }
}

// ---------------- pack gathered A rows into combined hi|lo tiles (R8-validated) -------
__global__ void __launch_bounds__(256) pack_a_kernel(const float* __restrict__ x) {
#if HAS_TCGEN05
    int mt = blockIdx.x, e = blockIdx.y;
    int n = d_cnt[e];
    if (mt * 128 >= n) return;
    int tid = threadIdx.x;
    int row = tid >> 1, half = tid & 1;
    int r = mt * 128 + row;
    int t = (r < n) ? d_tok[e * T_TOK + r] : -1;
    const float* xr = (t >= 0) ? (x + (size_t)t * H_DIM) : nullptr;

    for (int kc = 0; kc < 64; kc++) {
        float f[16];
        if (xr) {
#pragma unroll
            for (int j = 0; j < 4; j++)
                *(float4*)&f[j * 4] = *(const float4*)(xr + kc * 32 + half * 16 + j * 4);
        } else {
#pragma unroll
            for (int j = 0; j < 16; j++) f[j] = 0.f;
        }
        uint32_t hi[8], lo[8];
#pragma unroll
        for (int m = 0; m < 8; m++) {
            hi[m] = pack_bf16x2_hi(f[2 * m], f[2 * m + 1]);
            lo[m] = pack_bf16x2_lo(f[2 * m], f[2 * m + 1]);
        }
        size_t tb = PA_TILE(e, mt, kc);
#pragma unroll
        for (int q = 0; q < 2; q++) {
            uint32_t offh = swz((uint32_t)row * 128 + half * 32 + q * 16);
            uint32_t offl = swz((uint32_t)row * 128 + 64 + half * 32 + q * 16);
            *(uint4*)(d_pa + tb + offh) = ((uint4*)hi)[q];
            *(uint4*)(d_pa + tb + offl) = ((uint4*)lo)[q];
        }
    }
#endif
}

// ---------------- pack weights: 64-row input tiles -> TWO combined hi|lo output tiles --
__global__ void __launch_bounds__(256) pack_w2_kernel(
    const float* __restrict__ srcA, char* __restrict__ dA,
    const float* __restrict__ srcB, char* __restrict__ dB,
    int inner) {
#if HAS_TCGEN05
    int nt = blockIdx.x, kb = blockIdx.y;
    int e = blockIdx.z & 15, which = blockIdx.z >> 4;
    int KB = gridDim.y;
    const float* s = (which ? srcB : srcA) + (size_t)e * (KB * 64) * inner;
    char* d = which ? dB : dA;

    __shared__ float tile[64][129];
    int tid = threadIdx.x;
    for (int idx = tid; idx < 8192; idx += 256) {
        int k = idx >> 7, nn = idx & 127;
        tile[k][nn] = s[(size_t)(kb * 64 + k) * inner + nt * 128 + nn];
    }
    __syncthreads();
    size_t tb = ((((size_t)e * gridDim.x + nt) * (2 * KB)) + 2 * kb) << 14;
#pragma unroll
    for (int gi = 0; gi < 8; gi++) {
        int g = tid + gi * 256;
        int t2 = g >> 10;
        int g1 = g & 1023;
        int nn = g1 >> 3, q8 = g1 & 7;
        bool ishi = q8 < 4;
        int q = q8 & 3;
        uint32_t v[4];
#pragma unroll
        for (int m = 0; m < 4; m++) {
            float f0 = tile[t2 * 32 + q * 8 + 2 * m][nn];
            float f1 = tile[t2 * 32 + q * 8 + 2 * m + 1][nn];
            v[m] = ishi ? pack_bf16x2_hi(f0, f1) : pack_bf16x2_lo(f0, f1);
        }
        uint32_t off = swz((uint32_t)nn * 128 + (ishi ? q * 16 : 64 + q * 16));
        *(uint4*)(d + tb + ((size_t)t2 << 14) + off) = *(uint4*)v;
    }
#endif
}

// ================= tcgen05 MMA kernels (TMEM <= 256, all shapes validated) ============
// gu: M=128, N=128 gate + up. TMEM 256: gate@0, up@128. (R8-validated shape.)
__global__ void __launch_bounds__(256, 2) gu_mma_kernel() {
#if HAS_TCGEN05
    int e = blockIdx.z;
    int n = d_cnt[e];
    int mt = blockIdx.x;
    if (mt * 128 >= n) return;
    int ft = blockIdx.y;

    extern __shared__ char dyn_smem[];
    uint32_t sb = smem_to_u32(dyn_smem);
    int tid = threadIdx.x, wid = tid >> 5;

    if (wid == 0) TCGEN05_ALLOC(sb + SM_TMEMPTR, 256);
    if (tid == 0) {
        MBARRIER_INIT(sb + SM_MBARM, 1);
        MBARRIER_INIT(sb + SM_FULL0, 1);
        MBARRIER_INIT(sb + SM_FULL1, 1);
    }
    __syncthreads();
    uint32_t tmem;
    asm volatile("ld.shared.b32 %0, [%1];" : "=r"(tmem) : "r"(sb + SM_TMEMPTR));

    const char* pa = d_pa  + PA_TILE(e, mt, 0);
    const char* wg = d_wgp + WGU_TILE(e, ft, 0);
    const char* wu = d_wup + WGU_TILE(e, ft, 0);

    const int NC = 64;
    auto load_chunk = [&](int buf, int kc) {
        uint32_t st = sb + SM_STAGE0 + buf * STAGE_BYTES;
        uint32_t fb = sb + (buf ? SM_FULL1 : SM_FULL0);
        MBARRIER_EXPECT_TX(fb, STAGE_BYTES);
        size_t o = (size_t)kc << 14;
        bulk_cp(st + 0 * 16384, pa + o, 16384, fb);
        bulk_cp(st + 1 * 16384, wg + o, 16384, fb);
        bulk_cp(st + 2 * 16384, wu + o, 16384, fb);
    };

    if (tid == 0) { load_chunk(0, 0); load_chunk(1, 1); }

    for (int i = 0; i < NC; i++) {
        int buf = i & 1;
        MBARRIER_WAIT_PARITY(sb + (buf ? SM_FULL1 : SM_FULL0), (i >> 1) & 1);

        if (wid == 0 && elect_one_pred()) {
            uint32_t st = sb + SM_STAGE0 + buf * STAGE_BYTES;
            uint64_t a = MAKE_SMEM_DESC(st + 0 * 16384);
            uint64_t g = MAKE_SMEM_DESC(st + 1 * 16384);
            uint64_t u = MAKE_SMEM_DESC(st + 2 * 16384);
#pragma unroll
            for (int k = 0; k < 2; k++) {
                uint64_t o = (uint64_t)k * 2;   // hi K-step
                uint64_t ol = o + 4;            // matching lo K-step (+64B)
                bool acc = !(i == 0 && k == 0);
                mma_f16_ss(tmem + 0,   a + o,  g + o,  acc);
                mma_f16_ss(tmem + 0,   a + o,  g + ol, true);
                mma_f16_ss(tmem + 0,   a + ol, g + o,  true);
                mma_f16_ss(tmem + 128, a + o,  u + o,  acc);
                mma_f16_ss(tmem + 128, a + o,  u + ol, true);
                mma_f16_ss(tmem + 128, a + ol, u + o,  true);
            }
            TCGEN05_COMMIT(sb + SM_MBARM);
        }
        // tid0 observes MBARM phases strictly in order -> no parity aliasing.
        if (tid == 0 && i + 2 < NC) {
            MBARRIER_WAIT_PARITY(sb + SM_MBARM, i & 1);
            load_chunk(buf, i + 2);
        }
    }

    // Tail waits by tid0 only (sequential phase observer), then broadcast.
    if (tid == 0) {
        MBARRIER_WAIT_PARITY(sb + SM_MBARM, (NC - 2) & 1);
        MBARRIER_WAIT_PARITY(sb + SM_MBARM, (NC - 1) & 1);
    }
    __syncthreads();
    TCGEN05_FENCE_AFTER();

    if (wid < 4) {
        int lane = tid & 31;
        int lrow = wid * 32 + lane;
        uint32_t rg[32], ru[32];
#pragma unroll
        for (int cb = 0; cb < 4; cb++) {
            TCGEN05_LD_32X32B_X32(rg, tmem + cb * 32);
            TCGEN05_LD_32X32B_X32(ru, tmem + 128 + cb * 32);
            TCGEN05_WAIT_LD();
            uint32_t phi[16], plo[16];
#pragma unroll
            for (int j = 0; j < 16; j++) {
                float g0 = __uint_as_float(rg[2 * j]);
                float g1 = __uint_as_float(rg[2 * j + 1]);
                float u0 = __uint_as_float(ru[2 * j]);
                float u1 = __uint_as_float(ru[2 * j + 1]);
                float a0 = g0 / (1.f + __expf(-g0)) * u0;
                float a1 = g1 / (1.f + __expf(-g1)) * u1;
                phi[j] = pack_bf16x2_hi(a0, a1);
                plo[j] = pack_bf16x2_lo(a0, a1);
            }
            // cb block = 32 cols = exactly one K=32 act chunk
            int kc = ft * 4 + cb;
            size_t tb = ACT_TILE(e, mt, kc);
#pragma unroll
            for (int q = 0; q < 4; q++) {
                uint32_t offh = swz((uint32_t)lrow * 128 + q * 16);
                uint32_t offl = swz((uint32_t)lrow * 128 + 64 + q * 16);
                *(uint4*)(d_actp + tb + offh) = ((uint4*)phi)[q];
                *(uint4*)(d_actp + tb + offl) = ((uint4*)plo)[q];
            }
        }
    }
    __syncthreads();
    if (tid == 0) {
        MBARRIER_INVAL(sb + SM_MBARM);
        MBARRIER_INVAL(sb + SM_FULL0);
        MBARRIER_INVAL(sb + SM_FULL1);
    }
    __syncthreads();
    if (wid == 0) {
        TCGEN05_RELINQ();
        TCGEN05_DEALLOC(tmem, 256);
    }
#endif
}

// dn: M=256 (two M-tiles, dual accumulators M0@0, M1@128), N=128. (R10-validated shape.)
__global__ void __launch_bounds__(256, 2) dn_mma_kernel() {
#if HAS_TCGEN05
    int e = blockIdx.z;
    int n = d_cnt[e];
    int mt0 = blockIdx.x * 2;
    if (mt0 * 128 >= n) return;
    int ht = blockIdx.y;
    int col0 = ht * 128;

    extern __shared__ char dyn_smem[];
    uint32_t sb = smem_to_u32(dyn_smem);
    int tid = threadIdx.x, wid = tid >> 5;

    if (wid == 0) TCGEN05_ALLOC(sb + SM_TMEMPTR, 256);
    if (tid == 0) {
        MBARRIER_INIT(sb + SM_MBARM, 1);
        MBARRIER_INIT(sb + SM_FULL0, 1);
        MBARRIER_INIT(sb + SM_FULL1, 1);
    }
    __syncthreads();
    uint32_t tmem;
    asm volatile("ld.shared.b32 %0, [%1];" : "=r"(tmem) : "r"(sb + SM_TMEMPTR));

    const char* a0 = d_actp + ACT_TILE(e, mt0,     0);
    const char* a1 = d_actp + ACT_TILE(e, mt0 + 1, 0);
    const char* wd = d_wdp  + WD_TILE(e, ht, 0);

    const int NC = 32;
    auto load_chunk = [&](int buf, int kc) {
        uint32_t st = sb + SM_STAGE0 + buf * STAGE_BYTES;
        uint32_t fb = sb + (buf ? SM_FULL1 : SM_FULL0);
        MBARRIER_EXPECT_TX(fb, STAGE_BYTES);
        size_t o = (size_t)kc << 14;
        bulk_cp(st + 0 * 16384, a0 + o, 16384, fb);
        bulk_cp(st + 1 * 16384, a1 + o, 16384, fb);
        bulk_cp(st + 2 * 16384, wd + o, 16384, fb);
    };

    if (tid == 0) { load_chunk(0, 0); load_chunk(1, 1); }

    for (int i = 0; i < NC; i++) {
        int buf = i & 1;
        MBARRIER_WAIT_PARITY(sb + (buf ? SM_FULL1 : SM_FULL0), (i >> 1) & 1);

        if (wid == 0 && elect_one_pred()) {
            uint32_t st = sb + SM_STAGE0 + buf * STAGE_BYTES;
            uint64_t da0 = MAKE_SMEM_DESC(st + 0 * 16384);
            uint64_t da1 = MAKE_SMEM_DESC(st + 1 * 16384);
            uint64_t db  = MAKE_SMEM_DESC(st + 2 * 16384);
#pragma unroll
            for (int k = 0; k < 2; k++) {
                uint64_t o = (uint64_t)k * 2;
                uint64_t ol = o + 4;
                bool acc = !(i == 0 && k == 0);
                mma_f16_ss(tmem + 0,   da0 + o,  db + o,  acc);
                mma_f16_ss(tmem + 0,   da0 + o,  db + ol, true);
                mma_f16_ss(tmem + 0,   da0 + ol, db + o,  true);
                mma_f16_ss(tmem + 128, da1 + o,  db + o,  acc);
                mma_f16_ss(tmem + 128, da1 + o,  db + ol, true);
                mma_f16_ss(tmem + 128, da1 + ol, db + o,  true);
            }
            TCGEN05_COMMIT(sb + SM_MBARM);
        }
        if (tid == 0 && i + 2 < NC) {
            MBARRIER_WAIT_PARITY(sb + SM_MBARM, i & 1);
            load_chunk(buf, i + 2);
        }
    }

    if (tid == 0) {
        MBARRIER_WAIT_PARITY(sb + SM_MBARM, (NC - 2) & 1);
        MBARRIER_WAIT_PARITY(sb + SM_MBARM, (NC - 1) & 1);
    }
    __syncthreads();
    TCGEN05_FENCE_AFTER();

    if (wid < 4) {
        int lane = tid & 31;
        uint32_t r[32];
#pragma unroll
        for (int half = 0; half < 2; half++) {
            size_t rowidx = (size_t)e * T_TOK + (mt0 + half) * 128 + wid * 32 + lane;
#pragma unroll
            for (int cb = 0; cb < 4; cb++) {
                TCGEN05_LD_32X32B_X32(r, tmem + half * 128 + cb * 32);
                TCGEN05_WAIT_LD();
                uint4* dst = (uint4*)(d_ybuf + rowidx * H_DIM + col0 + cb * 32);
#pragma unroll
                for (int q = 0; q < 8; q++) dst[q] = ((uint4*)r)[q];
            }
        }
    }
    __syncthreads();
    if (tid == 0) {
        MBARRIER_INVAL(sb + SM_MBARM);
        MBARRIER_INVAL(sb + SM_FULL0);
        MBARRIER_INVAL(sb + SM_FULL1);
    }
    __syncthreads();
    if (wid == 0) {
        TCGEN05_RELINQ();
        TCGEN05_DEALLOC(tmem, 256);
    }
#endif
}

// ================= SIMT fallback path (validated; empty under tcgen05 build) ===========
__global__ void __launch_bounds__(256) gateup_simt_kernel(const float* __restrict__ x,
                                                          const float* __restrict__ Wg,
                                                          const float* __restrict__ Wu) {
#if !HAS_TCGEN05
    int e = blockIdx.z;
    int n = d_cnt[e];
    int row0 = blockIdx.x * 64;
    if (row0 >= n) return;
    int col0 = blockIdx.y * 64;

    __shared__ float Xs[64][17];
    __shared__ float Gs[16][64];
    __shared__ float Us[16][64];
    __shared__ int   toks[64];

    int tid = threadIdx.x;
    if (tid < 64) {
        int r = row0 + tid;
        toks[tid] = (r < n) ? d_tok[e * T_TOK + r] : -1;
    }
    __syncthreads();

    const float* wgp = Wg + (size_t)e * H_DIM * F_DIM;
    const float* wup = Wu + (size_t)e * H_DIM * F_DIM;

    float acc1[4][4], acc2[4][4];
#pragma unroll
    for (int i = 0; i < 4; i++)
#pragma unroll
        for (int j = 0; j < 4; j++) { acc1[i][j] = 0.f; acc2[i][j] = 0.f; }

    int tx = tid & 15, ty = tid >> 4;
    int xr = tid >> 2, xk = (tid & 3) * 4;
    int br = tid >> 4, bc = (tid & 15) * 4;

    int tk = toks[xr];
    const float* xrow = (tk >= 0) ? (x + (size_t)tk * H_DIM) : nullptr;

    for (int k0 = 0; k0 < H_DIM; k0 += 16) {
        float4 xv = make_float4(0.f, 0.f, 0.f, 0.f);
        if (xrow) xv = *(const float4*)(xrow + k0 + xk);
        Xs[xr][xk + 0] = xv.x; Xs[xr][xk + 1] = xv.y;
        Xs[xr][xk + 2] = xv.z; Xs[xr][xk + 3] = xv.w;

        *(float4*)&Gs[br][bc] = *(const float4*)(wgp + (size_t)(k0 + br) * F_DIM + col0 + bc);
        *(float4*)&Us[br][bc] = *(const float4*)(wup + (size_t)(k0 + br) * F_DIM + col0 + bc);
        __syncthreads();

#pragma unroll
        for (int kk = 0; kk < 16; kk++) {
            float a0 = Xs[ty * 4 + 0][kk];
            float a1 = Xs[ty * 4 + 1][kk];
            float a2 = Xs[ty * 4 + 2][kk];
            float a3 = Xs[ty * 4 + 3][kk];
            float4 bg = *(float4*)&Gs[kk][tx * 4];
            float4 bu = *(float4*)&Us[kk][tx * 4];

            acc1[0][0] += a0 * bg.x; acc1[0][1] += a0 * bg.y; acc1[0][2] += a0 * bg.z; acc1[0][3] += a0 * bg.w;
            acc1[1][0] += a1 * bg.x; acc1[1][1] += a1 * bg.y; acc1[1][2] += a1 * bg.z; acc1[1][3] += a1 * bg.w;
            acc1[2][0] += a2 * bg.x; acc1[2][1] += a2 * bg.y; acc1[2][2] += a2 * bg.z; acc1[2][3] += a2 * bg.w;
            acc1[3][0] += a3 * bg.x; acc1[3][1] += a3 * bg.y; acc1[3][2] += a3 * bg.z; acc1[3][3] += a3 * bg.w;

            acc2[0][0] += a0 * bu.x; acc2[0][1] += a0 * bu.y; acc2[0][2] += a0 * bu.z; acc2[0][3] += a0 * bu.w;
            acc2[1][0] += a1 * bu.x; acc2[1][1] += a1 * bu.y; acc2[1][2] += a1 * bu.z; acc2[1][3] += a1 * bu.w;
            acc2[2][0] += a2 * bu.x; acc2[2][1] += a2 * bu.y; acc2[2][2] += a2 * bu.z; acc2[2][3] += a2 * bu.w;
            acc2[3][0] += a3 * bu.x; acc2[3][1] += a3 * bu.y; acc2[3][2] += a3 * bu.z; acc2[3][3] += a3 * bu.w;
        }
        __syncthreads();
    }

#pragma unroll
    for (int i = 0; i < 4; i++) {
        int r = row0 + ty * 4 + i;
        if (r < n) {
            float* dst = d_act_f32 + ((size_t)e * T_TOK + r) * F_DIM + col0 + tx * 4;
#pragma unroll
            for (int j = 0; j < 4; j++) {
                float g = acc1[i][j];
                float s = g / (1.f + expf(-g));
                dst[j] = s * acc2[i][j];
            }
        }
    }
#endif
}

__global__ void __launch_bounds__(256) down_simt_kernel(const float* __restrict__ Wd) {
#if !HAS_TCGEN05
    int e = blockIdx.z;
    int n = d_cnt[e];
    int row0 = blockIdx.x * 64;
    if (row0 >= n) return;
    int col0 = blockIdx.y * 64;

    __shared__ float Xs[64][17];
    __shared__ float Bs[16][64];

    int tid = threadIdx.x;
    int tx = tid & 15, ty = tid >> 4;
    int xr = tid >> 2, xk = (tid & 3) * 4;
    int br = tid >> 4, bc = (tid & 15) * 4;

    const float* wdp = Wd + (size_t)e * F_DIM * H_DIM;
    const float* arow = (row0 + xr < n)
        ? (d_act_f32 + ((size_t)e * T_TOK + row0 + xr) * F_DIM) : nullptr;

    float acc[4][4];
#pragma unroll
    for (int i = 0; i < 4; i++)
#pragma unroll
        for (int j = 0; j < 4; j++) acc[i][j] = 0.f;

    for (int k0 = 0; k0 < F_DIM; k0 += 16) {
        float4 xv = make_float4(0.f, 0.f, 0.f, 0.f);
        if (arow) xv = *(const float4*)(arow + k0 + xk);
        Xs[xr][xk + 0] = xv.x; Xs[xr][xk + 1] = xv.y;
        Xs[xr][xk + 2] = xv.z; Xs[xr][xk + 3] = xv.w;

        *(float4*)&Bs[br][bc] = *(const float4*)(wdp + (size_t)(k0 + br) * H_DIM + col0 + bc);
        __syncthreads();

#pragma unroll
        for (int kk = 0; kk < 16; kk++) {
            float a0 = Xs[ty * 4 + 0][kk];
            float a1 = Xs[ty * 4 + 1][kk];
            float a2 = Xs[ty * 4 + 2][kk];
            float a3 = Xs[ty * 4 + 3][kk];
            float4 b = *(float4*)&Bs[kk][tx * 4];

            acc[0][0] += a0 * b.x; acc[0][1] += a0 * b.y; acc[0][2] += a0 * b.z; acc[0][3] += a0 * b.w;
            acc[1][0] += a1 * b.x; acc[1][1] += a1 * b.y; acc[1][2] += a1 * b.z; acc[1][3] += a1 * b.w;
            acc[2][0] += a2 * b.x; acc[2][1] += a2 * b.y; acc[2][2] += a2 * b.z; acc[2][3] += a2 * b.w;
            acc[3][0] += a3 * b.x; acc[3][1] += a3 * b.y; acc[3][2] += a3 * b.z; acc[3][3] += a3 * b.w;
        }
        __syncthreads();
    }

#pragma unroll
    for (int i = 0; i < 4; i++) {
        int r = row0 + ty * 4 + i;
        if (r < n) {
            float* dst = d_ybuf + ((size_t)e * T_TOK + r) * H_DIM + col0 + tx * 4;
#pragma unroll
            for (int j = 0; j < 4; j++) dst[j] = acc[i][j];
        }
    }
#endif
}

// ---------------- combine -----------------------------------------------------------
__global__ void __launch_bounds__(256) combine_kernel(float* __restrict__ out) {
    int t = blockIdx.x, tid = threadIdx.x;
    __shared__ int sl[K_TOP];
    __shared__ float sw[K_TOP];
    if (tid < K_TOP) {
        sl[tid] = d_slot[t * K_TOP + tid];
        sw[tid] = d_wk[t * K_TOP + tid];
    }
    __syncthreads();
    const float* y0 = d_ybuf + (size_t)sl[0] * H_DIM;
    const float* y1 = d_ybuf + (size_t)sl[1] * H_DIM;
    const float* y2 = d_ybuf + (size_t)sl[2] * H_DIM;
    const float* y3 = d_ybuf + (size_t)sl[3] * H_DIM;
    float w0 = sw[0], w1 = sw[1], w2 = sw[2], w3 = sw[3];
    float* op = out + (size_t)t * H_DIM;
    for (int h = tid * 4; h < H_DIM; h += 256 * 4) {
        float4 a = *(const float4*)(y0 + h);
        float4 b = *(const float4*)(y1 + h);
        float4 c = *(const float4*)(y2 + h);
        float4 d = *(const float4*)(y3 + h);
        float4 r;
        r.x = w0 * a.x + w1 * b.x + w2 * c.x + w3 * d.x;
        r.y = w0 * a.y + w1 * b.y + w2 * c.y + w3 * d.y;
        r.z = w0 * a.z + w1 * b.z + w2 * c.z + w3 * d.z;
        r.w = w0 * a.w + w1 * b.w + w2 * c.w + w3 * d.w;
        *(float4*)(op + h) = r;
    }
}

// ---------------- launch ---------------------------------------------------------------
extern "C" void kernel_launch(void* const* d_in, const int* in_sizes, int n_in,
                              void* d_out, int out_size) {
    const float* x     = (const float*)d_in[0];
    const float* wgate = (const float*)d_in[1];
    const float* Wg    = (const float*)d_in[2];
    const float* Wu    = (const float*)d_in[3];
    const float* Wd    = (const float*)d_in[4];
    float* out = (float*)d_out;

    float* logits_out;
    if (out_size >= T_TOK * H_DIM + T_TOK * E_NUM) {
        logits_out = out + (size_t)T_TOK * H_DIM;
    } else {
        static float* fb = nullptr;
        if (!fb) cudaGetSymbolAddress((void**)&fb, d_logits_fallback);
        logits_out = fb;
    }

    cudaFuncSetAttribute(gu_mma_kernel, cudaFuncAttributeMaxDynamicSharedMemorySize, MMA_SMEM);
    cudaFuncSetAttribute(dn_mma_kernel, cudaFuncAttributeMaxDynamicSharedMemorySize, MMA_SMEM);

    char *wgp, *wup, *wdp;
    cudaGetSymbolAddress((void**)&wgp, d_wgp);
    cudaGetSymbolAddress((void**)&wup, d_wup);
    cudaGetSymbolAddress((void**)&wdp, d_wdp);

    // Launch order: gu_mma_kernel is launch index 5 (ncu -s 5 -c 1 profiles it).
    init_kernel<<<1, 32>>>();                                                    // 0
    router_kernel<<<T_TOK, 256>>>(x, wgate, logits_out);                         // 1
    pack_w2_kernel<<<dim3(F_DIM / 128, H_DIM / 64, 2 * E_NUM), 256>>>(           // 2
        Wg, wgp, Wu, wup, F_DIM);
    pack_w2_kernel<<<dim3(H_DIM / 128, F_DIM / 64, E_NUM), 256>>>(               // 3
        Wd, wdp, Wd, wdp, H_DIM);
    pack_a_kernel<<<dim3(T_TOK / 128, E_NUM), 256>>>(x);                         // 4
    gu_mma_kernel<<<dim3(T_TOK / 128, F_DIM / 128, E_NUM), 256, MMA_SMEM>>>();   // 5 <- profiled
    dn_mma_kernel<<<dim3(T_TOK / 256, H_DIM / 128, E_NUM), 256, MMA_SMEM>>>();   // 6

    // ---- SIMT fallback path (no-op under the sm_103a build) ----
    gateup_simt_kernel<<<dim3(T_TOK / 64, F_DIM / 64, E_NUM), 256>>>(x, Wg, Wu);
    down_simt_kernel<<<dim3(T_TOK / 64, H_DIM / 64, E_NUM), 256>>>(Wd);

    combine_kernel<<<T_TOK, 256>>>(out);
}

// round 13
// speedup vs baseline: 1.0539x; 1.0539x over previous
#include <cuda_runtime.h>
#include <cuda_bf16.h>
#include <cstdint>
#include <math.h>

#define T_TOK 4096
#define H_DIM 2048
#define F_DIM 1024
#define E_NUM 16
#define K_TOP 4

#if defined(__CUDA_ARCH__) && (defined(__CUDA_ARCH_FEAT_SM103_ALL) || \
    defined(__CUDA_ARCH_FEAT_SM100_ALL) || defined(__CUDA_ARCH_SPECIFIC__) || \
    defined(__CUDA_ARCH_FAMILY_SPECIFIC__))
#define HAS_TCGEN05 1
#else
#define HAS_TCGEN05 0
#endif

// idesc kind::f16: dtype=F32(1<<4), atype=BF16(1<<7), btype=BF16(1<<10), (N/8)<<17, (M/16)<<24
#define IDESC_128x128 0x08200490u

#define SM_TMEMPTR 0
#define SM_MBARM   8
#define SM_FULL0   16
#define SM_FULL1   24
#define SM_STAGE0  1024
// combined hi|lo tiles: 16KB = 128 rows x [64B hi | 64B lo], K=32 per tile
#define STAGE_BYTES (4 * 16384)      // gu: A0,A1,Wg,Wu   dn: A0,A1,Wd0,Wd1
#define MMA_SMEM (1024 + 2 * STAGE_BYTES)   // 132KB -> 1 CTA/SM, TMEM 512

// packed tile addressing (combined hi|lo 16KB tiles, pre-swizzled SW128)
#define PA_TILE(e, mt, kc)  (((((size_t)(e) * 32 + (mt)) * 64) + (kc)) << 14)   // K=2048: 64 chunks
#define WGU_TILE(e, ft, kc) (((((size_t)(e) * 8  + (ft)) * 64) + (kc)) << 14)   // K=2048: 64 chunks
#define WD_TILE(e, ht, kc)  (((((size_t)(e) * 16 + (ht)) * 32) + (kc)) << 14)   // K=1024: 32 chunks
#define ACT_TILE(e, mt, kc) (((((size_t)(e) * 32 + (mt)) * 32) + (kc)) << 14)   // K=1024: 32 chunks

// ---------------- device scratch ---------------------------------------------------
__device__ int   d_cnt[E_NUM];
__device__ int   d_tok[E_NUM * T_TOK];
__device__ int   d_slot[T_TOK * K_TOP];
__device__ float d_wk[T_TOK * K_TOP];
__device__ __align__(128) char d_pa  [(size_t)E_NUM * T_TOK * H_DIM * 4];
__device__ __align__(128) char d_wgp [(size_t)E_NUM * F_DIM * H_DIM * 4];
__device__ __align__(128) char d_wup [(size_t)E_NUM * F_DIM * H_DIM * 4];
__device__ __align__(128) char d_wdp [(size_t)E_NUM * H_DIM * F_DIM * 4];
__device__ __align__(128) char d_actp[(size_t)E_NUM * T_TOK * F_DIM * 4];
__device__ float d_act_f32[(size_t)E_NUM * T_TOK * F_DIM];   // SIMT fallback path
__device__ float d_ybuf[(size_t)E_NUM * T_TOK * H_DIM];
__device__ float d_logits_fallback[(size_t)T_TOK * E_NUM];

// ---------------- portable PTX helpers ----------------------------------------------
__device__ __forceinline__ uint32_t elect_one_pred() {
    uint32_t pred;
    asm volatile("{\n\t.reg .pred p;\n\telect.sync _|p, 0xFFFFFFFF;\n\t"
                 "selp.b32 %0, 1, 0, p;\n\t}" : "=r"(pred));
    return pred;
}
__device__ __forceinline__ uint32_t smem_to_u32(const void* p) {
    uint32_t a;
    asm("{ .reg .u64 t; cvta.to.shared.u64 t, %1; cvt.u32.u64 %0, t; }" : "=r"(a) : "l"(p));
    return a;
}
__device__ __forceinline__ uint32_t swz(uint32_t off) { return off ^ ((off >> 3) & 0x70); }

#define MBARRIER_INIT(mbar, count) \
    asm volatile("mbarrier.init.shared.b64 [%0], %1;" :: "r"((uint32_t)(mbar)), "r"((uint32_t)(count)) : "memory")
#define MBARRIER_INVAL(mbar) \
    asm volatile("mbarrier.inval.shared.b64 [%0];" :: "r"((uint32_t)(mbar)) : "memory")
#define MBARRIER_EXPECT_TX(mbar, bytes) \
    asm volatile("mbarrier.arrive.expect_tx.shared.b64 _, [%0], %1;" :: "r"((uint32_t)(mbar)), "r"((uint32_t)(bytes)) : "memory")

#define MBARRIER_WAIT_PARITY(mbar_smem_addr, phase_parity) do { \
    uint32_t _mbar = (uint32_t)(mbar_smem_addr); \
    uint32_t _parity = (uint32_t)(phase_parity); \
    uint32_t _done; \
    asm volatile("{\n\t.reg .pred p;\n\t" \
        "mbarrier.try_wait.parity.acquire.cta.shared::cta.b64 p, [%1], %2;\n\t" \
        "selp.b32 %0, 1, 0, p;\n\t}" \
        : "=r"(_done) : "r"(_mbar), "r"(_parity) : "memory"); \
    if (!_done) { \
        asm volatile("{\n\t.reg .pred P1;\n\t" \
            "WAIT_LOOP_%=:\n\t" \
            "mbarrier.try_wait.parity.acquire.cta.shared::cta.b64 P1, [%0], %1, 0x989680;\n\t" \
            "@P1 bra.uni WAIT_DONE_%=;\n\t" \
            "bra.uni WAIT_LOOP_%=;\n\t" \
            "WAIT_DONE_%=:\n\t}" \
            :: "r"(_mbar), "r"(_parity) : "memory"); \
    } \
} while (0)

__device__ __forceinline__ uint32_t pack_bf16x2_hi(float f0, float f1) {
    __nv_bfloat162 h = __floats2bfloat162_rn(f0, f1);
    return *(uint32_t*)&h;
}
__device__ __forceinline__ uint32_t pack_bf16x2_lo(float f0, float f1) {
    __nv_bfloat16 h0 = __float2bfloat16(f0), h1 = __float2bfloat16(f1);
    __nv_bfloat162 l = __floats2bfloat162_rn(f0 - __bfloat162float(h0),
                                             f1 - __bfloat162float(h1));
    return *(uint32_t*)&l;
}

#if HAS_TCGEN05
#define TCGEN05_ALLOC(smem_addr, nCols) \
    asm volatile("tcgen05.alloc.cta_group::1.sync.aligned.shared::cta.b32 [%0], %1;" \
                 :: "r"((uint32_t)(smem_addr)), "r"((uint32_t)(nCols)) : "memory")
#define TCGEN05_RELINQ() \
    asm volatile("tcgen05.relinquish_alloc_permit.cta_group::1.sync.aligned;")
#define TCGEN05_DEALLOC(tmem, nCols) \
    asm volatile("tcgen05.dealloc.cta_group::1.sync.aligned.b32 %0, %1;" :: "r"(tmem), "r"((uint32_t)(nCols)))
#define TCGEN05_COMMIT(mbar) \
    asm volatile("tcgen05.commit.cta_group::1.mbarrier::arrive::one.shared::cluster.b64 [%0];" \
                 :: "r"((uint32_t)(mbar)) : "memory")
#define TCGEN05_FENCE_AFTER() asm volatile("tcgen05.fence::after_thread_sync;" ::: "memory")
#define TCGEN05_WAIT_LD()     asm volatile("tcgen05.wait::ld.sync.aligned;" ::: "memory")

#define TCGEN05_LD_32X32B_X32(r, tmem_addr) \
    asm volatile("tcgen05.ld.sync.aligned.32x32b.x32.b32 " \
        "{%0, %1, %2, %3, %4, %5, %6, %7, %8, %9, %10, %11, %12, %13, %14, %15, " \
        " %16, %17, %18, %19, %20, %21, %22, %23, %24, %25, %26, %27, %28, %29, %30, %31}, [%32];" \
        : "=r"((r)[0]),  "=r"((r)[1]),  "=r"((r)[2]),  "=r"((r)[3]), \
          "=r"((r)[4]),  "=r"((r)[5]),  "=r"((r)[6]),  "=r"((r)[7]), \
          "=r"((r)[8]),  "=r"((r)[9]),  "=r"((r)[10]), "=r"((r)[11]), \
          "=r"((r)[12]), "=r"((r)[13]), "=r"((r)[14]), "=r"((r)[15]), \
          "=r"((r)[16]), "=r"((r)[17]), "=r"((r)[18]), "=r"((r)[19]), \
          "=r"((r)[20]), "=r"((r)[21]), "=r"((r)[22]), "=r"((r)[23]), \
          "=r"((r)[24]), "=r"((r)[25]), "=r"((r)[26]), "=r"((r)[27]), \
          "=r"((r)[28]), "=r"((r)[29]), "=r"((r)[30]), "=r"((r)[31]) \
        : "r"(tmem_addr))

static constexpr uint64_t SMEM_DESC_BASE_SW128 =
    (uint64_t(2) << 61) | (uint64_t(1) << 46) | (uint64_t(64) << 32) | (uint64_t(1) << 16);
#define MAKE_SMEM_DESC(base_addr) (SMEM_DESC_BASE_SW128 | ((uint64_t)((base_addr) >> 4) & 0x3FFF))

__device__ __forceinline__ void mma_f16_ss(uint32_t d, uint64_t a, uint64_t b, bool acc) {
    uint32_t en = acc ? 1u : 0u;
    asm volatile("{\n\t.reg .pred p;\n\tsetp.ne.u32 p, %5, 0;\n\t"
                 "tcgen05.mma.cta_group::1.kind::f16 [%0], %1, %2, %3, {%4, %4, %4, %4}, p;\n\t}"
                 :: "r"(d), "l"(a), "l"(b), "r"(IDESC_128x128), "r"(0u), "r"(en) : "memory");
}

__device__ __forceinline__ void bulk_cp(uint32_t dst, const void* src, uint32_t bytes, uint32_t mbar) {
    asm volatile("cp.async.bulk.shared::cluster.global.mbarrier::complete_tx::bytes "
                 "[%0], [%1], %2, [%3];"
                 :: "r"(dst), "l"(src), "r"(bytes), "r"(mbar) : "memory");
}
#endif  // HAS_TCGEN05

// ---------------- init ---------------------------------------------------------------
__global__ void init_kernel() {
    if (threadIdx.x < E_NUM) d_cnt[threadIdx.x] = 0;
}

// ---------------- router (validated) ---------------------------------------------------
__global__ void __launch_bounds__(256) router_kernel(const float* __restrict__ x,
                                                     const float* __restrict__ wg,
                                                     float* __restrict__ logits_out) {
    int t = blockIdx.x, tid = threadIdx.x;
    float acc[E_NUM];
#pragma unroll
    for (int e = 0; e < E_NUM; e++) acc[e] = 0.f;
    const float* xr = x + (size_t)t * H_DIM;
    for (int h = tid; h < H_DIM; h += 256) {
        float xv = xr[h];
        const float* wrow = wg + (size_t)h * E_NUM;
#pragma unroll
        for (int e = 0; e < E_NUM; e++) acc[e] += xv * wrow[e];
    }
#pragma unroll
    for (int e = 0; e < E_NUM; e++) {
#pragma unroll
        for (int o = 16; o > 0; o >>= 1)
            acc[e] += __shfl_down_sync(0xffffffffu, acc[e], o);
    }
    __shared__ float sred[8][E_NUM];
    __shared__ float logits[E_NUM];
    int warp = tid >> 5, lane = tid & 31;
    if (lane == 0) {
#pragma unroll
        for (int e = 0; e < E_NUM; e++) sred[warp][e] = acc[e];
    }
    __syncthreads();
    if (tid < E_NUM) {
        float v = 0.f;
#pragma unroll
        for (int w = 0; w < 8; w++) v += sred[w][tid];
        logits[tid] = v;
        logits_out[(size_t)t * E_NUM + tid] = v;
    }
    __syncthreads();
    if (tid == 0) {
        float l[E_NUM];
#pragma unroll
        for (int e = 0; e < E_NUM; e++) l[e] = logits[e];
        int sel[K_TOP]; float selv[K_TOP]; bool used[E_NUM];
#pragma unroll
        for (int e = 0; e < E_NUM; e++) used[e] = false;
#pragma unroll
        for (int k = 0; k < K_TOP; k++) {
            int best = -1; float bv = -1e30f;
            for (int e = 0; e < E_NUM; e++)
                if (!used[e] && l[e] > bv) { bv = l[e]; best = e; }
            used[best] = true; sel[k] = best; selv[k] = bv;
        }
        float m = selv[0], w[K_TOP], sum = 0.f;
#pragma unroll
        for (int k = 0; k < K_TOP; k++) { w[k] = expf(selv[k] - m); sum += w[k]; }
        float inv = 1.f / sum;
#pragma unroll
        for (int k = 0; k < K_TOP; k++) {
            int e = sel[k];
            int pos = atomicAdd(&d_cnt[e], 1);
            d_tok[e * T_TOK + pos] = t;
            d_slot[t * K_TOP + k] = e * T_TOK + pos;
            d_wk[t * K_TOP + k] = w[k] * inv;
        }
    }
}

// ---------------- pack gathered A rows into combined hi|lo tiles (validated) ----------
__global__ void __launch_bounds__(256) pack_a_kernel(const float* __restrict__ x) {
#if HAS_TCGEN05
    int mt = blockIdx.x, e = blockIdx.y;
    int n = d_cnt[e];
    if (mt * 128 >= n) return;
    int tid = threadIdx.x;
    int row = tid >> 1, half = tid & 1;
    int r = mt * 128 + row;
    int t = (r < n) ? d_tok[e * T_TOK + r] : -1;
    const float* xr = (t >= 0) ? (x + (size_t)t * H_DIM) : nullptr;

    for (int kc = 0; kc < 64; kc++) {
        float f[16];
        if (xr) {
#pragma unroll
            for (int j = 0; j < 4; j++)
                *(float4*)&f[j * 4] = *(const float4*)(xr + kc * 32 + half * 16 + j * 4);
        } else {
#pragma unroll
            for (int j = 0; j < 16; j++) f[j] = 0.f;
        }
        uint32_t hi[8], lo[8];
#pragma unroll
        for (int m = 0; m < 8; m++) {
            hi[m] = pack_bf16x2_hi(f[2 * m], f[2 * m + 1]);
            lo[m] = pack_bf16x2_lo(f[2 * m], f[2 * m + 1]);
        }
        size_t tb = PA_TILE(e, mt, kc);
#pragma unroll
        for (int q = 0; q < 2; q++) {
            uint32_t offh = swz((uint32_t)row * 128 + half * 32 + q * 16);
            uint32_t offl = swz((uint32_t)row * 128 + 64 + half * 32 + q * 16);
            *(uint4*)(d_pa + tb + offh) = ((uint4*)hi)[q];
            *(uint4*)(d_pa + tb + offl) = ((uint4*)lo)[q];
        }
    }
#endif
}

// ---------------- pack weights (validated in R12) --------------------------------------
__global__ void __launch_bounds__(256) pack_w2_kernel(
    const float* __restrict__ srcA, char* __restrict__ dA,
    const float* __restrict__ srcB, char* __restrict__ dB,
    int inner) {
#if HAS_TCGEN05
    int nt = blockIdx.x, kb = blockIdx.y;
    int e = blockIdx.z & 15, which = blockIdx.z >> 4;
    int KB = gridDim.y;
    const float* s = (which ? srcB : srcA) + (size_t)e * (KB * 64) * inner;
    char* d = which ? dB : dA;

    __shared__ float tile[64][129];
    int tid = threadIdx.x;
    for (int idx = tid; idx < 8192; idx += 256) {
        int k = idx >> 7, nn = idx & 127;
        tile[k][nn] = s[(size_t)(kb * 64 + k) * inner + nt * 128 + nn];
    }
    __syncthreads();
    size_t tb = ((((size_t)e * gridDim.x + nt) * (2 * KB)) + 2 * kb) << 14;
#pragma unroll
    for (int gi = 0; gi < 8; gi++) {
        int g = tid + gi * 256;
        int t2 = g >> 10;
        int g1 = g & 1023;
        int nn = g1 >> 3, q8 = g1 & 7;
        bool ishi = q8 < 4;
        int q = q8 & 3;
        uint32_t v[4];
#pragma unroll
        for (int m = 0; m < 4; m++) {
            float f0 = tile[t2 * 32 + q * 8 + 2 * m][nn];
            float f1 = tile[t2 * 32 + q * 8 + 2 * m + 1][nn];
            v[m] = ishi ? pack_bf16x2_hi(f0, f1) : pack_bf16x2_lo(f0, f1);
        }
        uint32_t off = swz((uint32_t)nn * 128 + (ishi ? q * 16 : 64 + q * 16));
        *(uint4*)(d + tb + ((size_t)t2 << 14) + off) = *(uint4*)v;
    }
#endif
}

// ================= tcgen05 MMA kernels (M=256 tiles, TMEM 512) =========================
// gu: M=256 (two M-tiles), N=128. TMEM: M0g@0, M0u@128, M1g@256, M1u@384.
__global__ void __launch_bounds__(256, 1) gu_mma_kernel() {
#if HAS_TCGEN05
    int e = blockIdx.z;
    int n = d_cnt[e];
    int mt0 = blockIdx.x * 2;
    if (mt0 * 128 >= n) return;
    int ft = blockIdx.y;

    extern __shared__ char dyn_smem[];
    uint32_t sb = smem_to_u32(dyn_smem);
    int tid = threadIdx.x, wid = tid >> 5;

    if (wid == 0) TCGEN05_ALLOC(sb + SM_TMEMPTR, 512);
    if (tid == 0) {
        MBARRIER_INIT(sb + SM_MBARM, 1);
        MBARRIER_INIT(sb + SM_FULL0, 1);
        MBARRIER_INIT(sb + SM_FULL1, 1);
    }
    __syncthreads();
    uint32_t tmem;
    asm volatile("ld.shared.b32 %0, [%1];" : "=r"(tmem) : "r"(sb + SM_TMEMPTR));

    const char* pa0 = d_pa  + PA_TILE(e, mt0,     0);
    const char* pa1 = d_pa  + PA_TILE(e, mt0 + 1, 0);
    const char* wg  = d_wgp + WGU_TILE(e, ft, 0);
    const char* wu  = d_wup + WGU_TILE(e, ft, 0);

    const int NC = 64;
    auto load_chunk = [&](int buf, int kc) {
        uint32_t st = sb + SM_STAGE0 + buf * STAGE_BYTES;
        uint32_t fb = sb + (buf ? SM_FULL1 : SM_FULL0);
        MBARRIER_EXPECT_TX(fb, STAGE_BYTES);
        size_t o = (size_t)kc << 14;
        bulk_cp(st + 0 * 16384, pa0 + o, 16384, fb);
        bulk_cp(st + 1 * 16384, pa1 + o, 16384, fb);
        bulk_cp(st + 2 * 16384, wg + o, 16384, fb);
        bulk_cp(st + 3 * 16384, wu + o, 16384, fb);
    };

    if (tid == 0) { load_chunk(0, 0); load_chunk(1, 1); }

    for (int i = 0; i < NC; i++) {
        int buf = i & 1;
        MBARRIER_WAIT_PARITY(sb + (buf ? SM_FULL1 : SM_FULL0), (i >> 1) & 1);

        if (wid == 0 && elect_one_pred()) {
            uint32_t st = sb + SM_STAGE0 + buf * STAGE_BYTES;
            uint64_t a0 = MAKE_SMEM_DESC(st + 0 * 16384);
            uint64_t a1 = MAKE_SMEM_DESC(st + 1 * 16384);
            uint64_t g  = MAKE_SMEM_DESC(st + 2 * 16384);
            uint64_t u  = MAKE_SMEM_DESC(st + 3 * 16384);
#pragma unroll
            for (int k = 0; k < 2; k++) {
                uint64_t o = (uint64_t)k * 2;
                uint64_t ol = o + 4;
                bool acc = !(i == 0 && k == 0);
                mma_f16_ss(tmem + 0,   a0 + o,  g + o,  acc);
                mma_f16_ss(tmem + 0,   a0 + o,  g + ol, true);
                mma_f16_ss(tmem + 0,   a0 + ol, g + o,  true);
                mma_f16_ss(tmem + 128, a0 + o,  u + o,  acc);
                mma_f16_ss(tmem + 128, a0 + o,  u + ol, true);
                mma_f16_ss(tmem + 128, a0 + ol, u + o,  true);
                mma_f16_ss(tmem + 256, a1 + o,  g + o,  acc);
                mma_f16_ss(tmem + 256, a1 + o,  g + ol, true);
                mma_f16_ss(tmem + 256, a1 + ol, g + o,  true);
                mma_f16_ss(tmem + 384, a1 + o,  u + o,  acc);
                mma_f16_ss(tmem + 384, a1 + o,  u + ol, true);
                mma_f16_ss(tmem + 384, a1 + ol, u + o,  true);
            }
            TCGEN05_COMMIT(sb + SM_MBARM);
        }
        // tid0 observes MBARM phases strictly in order -> no parity aliasing.
        if (tid == 0 && i + 2 < NC) {
            MBARRIER_WAIT_PARITY(sb + SM_MBARM, i & 1);
            load_chunk(buf, i + 2);
        }
    }

    if (tid == 0) {
        MBARRIER_WAIT_PARITY(sb + SM_MBARM, (NC - 2) & 1);
        MBARRIER_WAIT_PARITY(sb + SM_MBARM, (NC - 1) & 1);
    }
    __syncthreads();
    TCGEN05_FENCE_AFTER();

    if (wid < 4) {
        int lane = tid & 31;
        int lrow = wid * 32 + lane;
        uint32_t rg[32], ru[32];
#pragma unroll
        for (int half = 0; half < 2; half++) {
#pragma unroll
            for (int cb = 0; cb < 4; cb++) {
                TCGEN05_LD_32X32B_X32(rg, tmem + half * 256 + cb * 32);
                TCGEN05_LD_32X32B_X32(ru, tmem + half * 256 + 128 + cb * 32);
                TCGEN05_WAIT_LD();
                uint32_t phi[16], plo[16];
#pragma unroll
                for (int j = 0; j < 16; j++) {
                    float g0 = __uint_as_float(rg[2 * j]);
                    float g1 = __uint_as_float(rg[2 * j + 1]);
                    float u0 = __uint_as_float(ru[2 * j]);
                    float u1 = __uint_as_float(ru[2 * j + 1]);
                    float a0 = g0 / (1.f + __expf(-g0)) * u0;
                    float a1 = g1 / (1.f + __expf(-g1)) * u1;
                    phi[j] = pack_bf16x2_hi(a0, a1);
                    plo[j] = pack_bf16x2_lo(a0, a1);
                }
                int kc = ft * 4 + cb;
                size_t tb = ACT_TILE(e, mt0 + half, kc);
#pragma unroll
                for (int q = 0; q < 4; q++) {
                    uint32_t offh = swz((uint32_t)lrow * 128 + q * 16);
                    uint32_t offl = swz((uint32_t)lrow * 128 + 64 + q * 16);
                    *(uint4*)(d_actp + tb + offh) = ((uint4*)phi)[q];
                    *(uint4*)(d_actp + tb + offl) = ((uint4*)plo)[q];
                }
            }
        }
    }
    __syncthreads();
    if (tid == 0) {
        MBARRIER_INVAL(sb + SM_MBARM);
        MBARRIER_INVAL(sb + SM_FULL0);
        MBARRIER_INVAL(sb + SM_FULL1);
    }
    __syncthreads();
    if (wid == 0) {
        TCGEN05_RELINQ();
        TCGEN05_DEALLOC(tmem, 512);
    }
#endif
}

// dn: M=256, N=256. TMEM: M0N0@0, M0N1@128, M1N0@256, M1N1@384.
__global__ void __launch_bounds__(256, 1) dn_mma_kernel() {
#if HAS_TCGEN05
    int e = blockIdx.z;
    int n = d_cnt[e];
    int mt0 = blockIdx.x * 2;
    if (mt0 * 128 >= n) return;
    int ht0 = blockIdx.y * 2;

    extern __shared__ char dyn_smem[];
    uint32_t sb = smem_to_u32(dyn_smem);
    int tid = threadIdx.x, wid = tid >> 5;

    if (wid == 0) TCGEN05_ALLOC(sb + SM_TMEMPTR, 512);
    if (tid == 0) {
        MBARRIER_INIT(sb + SM_MBARM, 1);
        MBARRIER_INIT(sb + SM_FULL0, 1);
        MBARRIER_INIT(sb + SM_FULL1, 1);
    }
    __syncthreads();
    uint32_t tmem;
    asm volatile("ld.shared.b32 %0, [%1];" : "=r"(tmem) : "r"(sb + SM_TMEMPTR));

    const char* a0 = d_actp + ACT_TILE(e, mt0,     0);
    const char* a1 = d_actp + ACT_TILE(e, mt0 + 1, 0);
    const char* w0 = d_wdp  + WD_TILE(e, ht0,     0);
    const char* w1 = d_wdp  + WD_TILE(e, ht0 + 1, 0);

    const int NC = 32;
    auto load_chunk = [&](int buf, int kc) {
        uint32_t st = sb + SM_STAGE0 + buf * STAGE_BYTES;
        uint32_t fb = sb + (buf ? SM_FULL1 : SM_FULL0);
        MBARRIER_EXPECT_TX(fb, STAGE_BYTES);
        size_t o = (size_t)kc << 14;
        bulk_cp(st + 0 * 16384, a0 + o, 16384, fb);
        bulk_cp(st + 1 * 16384, a1 + o, 16384, fb);
        bulk_cp(st + 2 * 16384, w0 + o, 16384, fb);
        bulk_cp(st + 3 * 16384, w1 + o, 16384, fb);
    };

    if (tid == 0) { load_chunk(0, 0); load_chunk(1, 1); }

    for (int i = 0; i < NC; i++) {
        int buf = i & 1;
        MBARRIER_WAIT_PARITY(sb + (buf ? SM_FULL1 : SM_FULL0), (i >> 1) & 1);

        if (wid == 0 && elect_one_pred()) {
            uint32_t st = sb + SM_STAGE0 + buf * STAGE_BYTES;
            uint64_t da0 = MAKE_SMEM_DESC(st + 0 * 16384);
            uint64_t da1 = MAKE_SMEM_DESC(st + 1 * 16384);
            uint64_t db0 = MAKE_SMEM_DESC(st + 2 * 16384);
            uint64_t db1 = MAKE_SMEM_DESC(st + 3 * 16384);
#pragma unroll
            for (int k = 0; k < 2; k++) {
                uint64_t o = (uint64_t)k * 2;
                uint64_t ol = o + 4;
                bool acc = !(i == 0 && k == 0);
                mma_f16_ss(tmem + 0,   da0 + o,  db0 + o,  acc);
                mma_f16_ss(tmem + 0,   da0 + o,  db0 + ol, true);
                mma_f16_ss(tmem + 0,   da0 + ol, db0 + o,  true);
                mma_f16_ss(tmem + 128, da0 + o,  db1 + o,  acc);
                mma_f16_ss(tmem + 128, da0 + o,  db1 + ol, true);
                mma_f16_ss(tmem + 128, da0 + ol, db1 + o,  true);
                mma_f16_ss(tmem + 256, da1 + o,  db0 + o,  acc);
                mma_f16_ss(tmem + 256, da1 + o,  db0 + ol, true);
                mma_f16_ss(tmem + 256, da1 + ol, db0 + o,  true);
                mma_f16_ss(tmem + 384, da1 + o,  db1 + o,  acc);
                mma_f16_ss(tmem + 384, da1 + o,  db1 + ol, true);
                mma_f16_ss(tmem + 384, da1 + ol, db1 + o,  true);
            }
            TCGEN05_COMMIT(sb + SM_MBARM);
        }
        if (tid == 0 && i + 2 < NC) {
            MBARRIER_WAIT_PARITY(sb + SM_MBARM, i & 1);
            load_chunk(buf, i + 2);
        }
    }

    if (tid == 0) {
        MBARRIER_WAIT_PARITY(sb + SM_MBARM, (NC - 2) & 1);
        MBARRIER_WAIT_PARITY(sb + SM_MBARM, (NC - 1) & 1);
    }
    __syncthreads();
    TCGEN05_FENCE_AFTER();

    if (wid < 4) {
        int lane = tid & 31;
        uint32_t r[32];
#pragma unroll
        for (int mh = 0; mh < 2; mh++) {
            size_t rowidx = (size_t)e * T_TOK + (mt0 + mh) * 128 + wid * 32 + lane;
#pragma unroll
            for (int nh = 0; nh < 2; nh++) {
                int col0 = (ht0 + nh) * 128;
#pragma unroll
                for (int cb = 0; cb < 4; cb++) {
                    TCGEN05_LD_32X32B_X32(r, tmem + mh * 256 + nh * 128 + cb * 32);
                    TCGEN05_WAIT_LD();
                    uint4* dst = (uint4*)(d_ybuf + rowidx * H_DIM + col0 + cb * 32);
#pragma unroll
                    for (int q = 0; q < 8; q++) dst[q] = ((uint4*)r)[q];
                }
            }
        }
    }
    __syncthreads();
    if (tid == 0) {
        MBARRIER_INVAL(sb + SM_MBARM);
        MBARRIER_INVAL(sb + SM_FULL0);
        MBARRIER_INVAL(sb + SM_FULL1);
    }
    __syncthreads();
    if (wid == 0) {
        TCGEN05_RELINQ();
        TCGEN05_DEALLOC(tmem, 512);
    }
#endif
}

// ================= SIMT fallback path (validated; empty under tcgen05 build) ===========
__global__ void __launch_bounds__(256) gateup_simt_kernel(const float* __restrict__ x,
                                                          const float* __restrict__ Wg,
                                                          const float* __restrict__ Wu) {
#if !HAS_TCGEN05
    int e = blockIdx.z;
    int n = d_cnt[e];
    int row0 = blockIdx.x * 64;
    if (row0 >= n) return;
    int col0 = blockIdx.y * 64;

    __shared__ float Xs[64][17];
    __shared__ float Gs[16][64];
    __shared__ float Us[16][64];
    __shared__ int   toks[64];

    int tid = threadIdx.x;
    if (tid < 64) {
        int r = row0 + tid;
        toks[tid] = (r < n) ? d_tok[e * T_TOK + r] : -1;
    }
    __syncthreads();

    const float* wgp = Wg + (size_t)e * H_DIM * F_DIM;
    const float* wup = Wu + (size_t)e * H_DIM * F_DIM;

    float acc1[4][4], acc2[4][4];
#pragma unroll
    for (int i = 0; i < 4; i++)
#pragma unroll
        for (int j = 0; j < 4; j++) { acc1[i][j] = 0.f; acc2[i][j] = 0.f; }

    int tx = tid & 15, ty = tid >> 4;
    int xr = tid >> 2, xk = (tid & 3) * 4;
    int br = tid >> 4, bc = (tid & 15) * 4;

    int tk = toks[xr];
    const float* xrow = (tk >= 0) ? (x + (size_t)tk * H_DIM) : nullptr;

    for (int k0 = 0; k0 < H_DIM; k0 += 16) {
        float4 xv = make_float4(0.f, 0.f, 0.f, 0.f);
        if (xrow) xv = *(const float4*)(xrow + k0 + xk);
        Xs[xr][xk + 0] = xv.x; Xs[xr][xk + 1] = xv.y;
        Xs[xr][xk + 2] = xv.z; Xs[xr][xk + 3] = xv.w;

        *(float4*)&Gs[br][bc] = *(const float4*)(wgp + (size_t)(k0 + br) * F_DIM + col0 + bc);
        *(float4*)&Us[br][bc] = *(const float4*)(wup + (size_t)(k0 + br) * F_DIM + col0 + bc);
        __syncthreads();

#pragma unroll
        for (int kk = 0; kk < 16; kk++) {
            float a0 = Xs[ty * 4 + 0][kk];
            float a1 = Xs[ty * 4 + 1][kk];
            float a2 = Xs[ty * 4 + 2][kk];
            float a3 = Xs[ty * 4 + 3][kk];
            float4 bg = *(float4*)&Gs[kk][tx * 4];
            float4 bu = *(float4*)&Us[kk][tx * 4];

            acc1[0][0] += a0 * bg.x; acc1[0][1] += a0 * bg.y; acc1[0][2] += a0 * bg.z; acc1[0][3] += a0 * bg.w;
            acc1[1][0] += a1 * bg.x; acc1[1][1] += a1 * bg.y; acc1[1][2] += a1 * bg.z; acc1[1][3] += a1 * bg.w;
            acc1[2][0] += a2 * bg.x; acc1[2][1] += a2 * bg.y; acc1[2][2] += a2 * bg.z; acc1[2][3] += a2 * bg.w;
            acc1[3][0] += a3 * bg.x; acc1[3][1] += a3 * bg.y; acc1[3][2] += a3 * bg.z; acc1[3][3] += a3 * bg.w;

            acc2[0][0] += a0 * bu.x; acc2[0][1] += a0 * bu.y; acc2[0][2] += a0 * bu.z; acc2[0][3] += a0 * bu.w;
            acc2[1][0] += a1 * bu.x; acc2[1][1] += a1 * bu.y; acc2[1][2] += a1 * bu.z; acc2[1][3] += a1 * bu.w;
            acc2[2][0] += a2 * bu.x; acc2[2][1] += a2 * bu.y; acc2[2][2] += a2 * bu.z; acc2[2][3] += a2 * bu.w;
            acc2[3][0] += a3 * bu.x; acc2[3][1] += a3 * bu.y; acc2[3][2] += a3 * bu.z; acc2[3][3] += a3 * bu.w;
        }
        __syncthreads();
    }

#pragma unroll
    for (int i = 0; i < 4; i++) {
        int r = row0 + ty * 4 + i;
        if (r < n) {
            float* dst = d_act_f32 + ((size_t)e * T_TOK + r) * F_DIM + col0 + tx * 4;
#pragma unroll
            for (int j = 0; j < 4; j++) {
                float g = acc1[i][j];
                float s = g / (1.f + expf(-g));
                dst[j] = s * acc2[i][j];
            }
        }
    }
#endif
}

__global__ void __launch_bounds__(256) down_simt_kernel(const float* __restrict__ Wd) {
#if !HAS_TCGEN05
    int e = blockIdx.z;
    int n = d_cnt[e];
    int row0 = blockIdx.x * 64;
    if (row0 >= n) return;
    int col0 = blockIdx.y * 64;

    __shared__ float Xs[64][17];
    __shared__ float Bs[16][64];

    int tid = threadIdx.x;
    int tx = tid & 15, ty = tid >> 4;
    int xr = tid >> 2, xk = (tid & 3) * 4;
    int br = tid >> 4, bc = (tid & 15) * 4;

    const float* wdp = Wd + (size_t)e * F_DIM * H_DIM;
    const float* arow = (row0 + xr < n)
        ? (d_act_f32 + ((size_t)e * T_TOK + row0 + xr) * F_DIM) : nullptr;

    float acc[4][4];
#pragma unroll
    for (int i = 0; i < 4; i++)
#pragma unroll
        for (int j = 0; j < 4; j++) acc[i][j] = 0.f;

    for (int k0 = 0; k0 < F_DIM; k0 += 16) {
        float4 xv = make_float4(0.f, 0.f, 0.f, 0.f);
        if (arow) xv = *(const float4*)(arow + k0 + xk);
        Xs[xr][xk + 0] = xv.x; Xs[xr][xk + 1] = xv.y;
        Xs[xr][xk + 2] = xv.z; Xs[xr][xk + 3] = xv.w;

        *(float4*)&Bs[br][bc] = *(const float4*)(wdp + (size_t)(k0 + br) * H_DIM + col0 + bc);
        __syncthreads();

#pragma unroll
        for (int kk = 0; kk < 16; kk++) {
            float a0 = Xs[ty * 4 + 0][kk];
            float a1 = Xs[ty * 4 + 1][kk];
            float a2 = Xs[ty * 4 + 2][kk];
            float a3 = Xs[ty * 4 + 3][kk];
            float4 b = *(float4*)&Bs[kk][tx * 4];

            acc[0][0] += a0 * b.x; acc[0][1] += a0 * b.y; acc[0][2] += a0 * b.z; acc[0][3] += a0 * b.w;
            acc[1][0] += a1 * b.x; acc[1][1] += a1 * b.y; acc[1][2] += a1 * b.z; acc[1][3] += a1 * b.w;
            acc[2][0] += a2 * b.x; acc[2][1] += a2 * b.y; acc[2][2] += a2 * b.z; acc[2][3] += a2 * b.w;
            acc[3][0] += a3 * b.x; acc[3][1] += a3 * b.y; acc[3][2] += a3 * b.z; acc[3][3] += a3 * b.w;
        }
        __syncthreads();
    }

#pragma unroll
    for (int i = 0; i < 4; i++) {
        int r = row0 + ty * 4 + i;
        if (r < n) {
            float* dst = d_ybuf + ((size_t)e * T_TOK + r) * H_DIM + col0 + tx * 4;
#pragma unroll
            for (int j = 0; j < 4; j++) dst[j] = acc[i][j];
        }
    }
#endif
}

// ---------------- combine -----------------------------------------------------------
__global__ void __launch_bounds__(256) combine_kernel(float* __restrict__ out) {
    int t = blockIdx.x, tid = threadIdx.x;
    __shared__ int sl[K_TOP];
    __shared__ float sw[K_TOP];
    if (tid < K_TOP) {
        sl[tid] = d_slot[t * K_TOP + tid];
        sw[tid] = d_wk[t * K_TOP + tid];
    }
    __syncthreads();
    const float* y0 = d_ybuf + (size_t)sl[0] * H_DIM;
    const float* y1 = d_ybuf + (size_t)sl[1] * H_DIM;
    const float* y2 = d_ybuf + (size_t)sl[2] * H_DIM;
    const float* y3 = d_ybuf + (size_t)sl[3] * H_DIM;
    float w0 = sw[0], w1 = sw[1], w2 = sw[2], w3 = sw[3];
    float* op = out + (size_t)t * H_DIM;
    for (int h = tid * 4; h < H_DIM; h += 256 * 4) {
        float4 a = *(const float4*)(y0 + h);
        float4 b = *(const float4*)(y1 + h);
        float4 c = *(const float4*)(y2 + h);
        float4 d = *(const float4*)(y3 + h);
        float4 r;
        r.x = w0 * a.x + w1 * b.x + w2 * c.x + w3 * d.x;
        r.y = w0 * a.y + w1 * b.y + w2 * c.y + w3 * d.y;
        r.z = w0 * a.z + w1 * b.z + w2 * c.z + w3 * d.z;
        r.w = w0 * a.w + w1 * b.w + w2 * c.w + w3 * d.w;
        *(float4*)(op + h) = r;
    }
}

// ---------------- launch ---------------------------------------------------------------
extern "C" void kernel_launch(void* const* d_in, const int* in_sizes, int n_in,
                              void* d_out, int out_size) {
    const float* x     = (const float*)d_in[0];
    const float* wgate = (const float*)d_in[1];
    const float* Wg    = (const float*)d_in[2];
    const float* Wu    = (const float*)d_in[3];
    const float* Wd    = (const float*)d_in[4];
    float* out = (float*)d_out;

    float* logits_out;
    if (out_size >= T_TOK * H_DIM + T_TOK * E_NUM) {
        logits_out = out + (size_t)T_TOK * H_DIM;
    } else {
        static float* fb = nullptr;
        if (!fb) cudaGetSymbolAddress((void**)&fb, d_logits_fallback);
        logits_out = fb;
    }

    cudaFuncSetAttribute(gu_mma_kernel, cudaFuncAttributeMaxDynamicSharedMemorySize, MMA_SMEM);
    cudaFuncSetAttribute(dn_mma_kernel, cudaFuncAttributeMaxDynamicSharedMemorySize, MMA_SMEM);

    char *wgp, *wup, *wdp;
    cudaGetSymbolAddress((void**)&wgp, d_wgp);
    cudaGetSymbolAddress((void**)&wup, d_wup);
    cudaGetSymbolAddress((void**)&wdp, d_wdp);

    // Launch order: gu_mma_kernel is launch index 5 (ncu -s 5 -c 1 profiles it).
    init_kernel<<<1, 32>>>();                                                    // 0
    router_kernel<<<T_TOK, 256>>>(x, wgate, logits_out);                         // 1
    pack_w2_kernel<<<dim3(F_DIM / 128, H_DIM / 64, 2 * E_NUM), 256>>>(           // 2
        Wg, wgp, Wu, wup, F_DIM);
    pack_w2_kernel<<<dim3(H_DIM / 128, F_DIM / 64, E_NUM), 256>>>(               // 3
        Wd, wdp, Wd, wdp, H_DIM);
    pack_a_kernel<<<dim3(T_TOK / 128, E_NUM), 256>>>(x);                         // 4
    gu_mma_kernel<<<dim3(T_TOK / 256, F_DIM / 128, E_NUM), 256, MMA_SMEM>>>();   // 5 <- profiled
    dn_mma_kernel<<<dim3(T_TOK / 256, H_DIM / 256, E_NUM), 256, MMA_SMEM>>>();   // 6

    // ---- SIMT fallback path (no-op under the sm_103a build) ----
    gateup_simt_kernel<<<dim3(T_TOK / 64, F_DIM / 64, E_NUM), 256>>>(x, Wg, Wu);
    down_simt_kernel<<<dim3(T_TOK / 64, H_DIM / 64, E_NUM), 256>>>(Wd);

    combine_kernel<<<T_TOK, 256>>>(out);
}

// round 17
// speedup vs baseline: 1.0666x; 1.0121x over previous
#include <cuda_runtime.h>
#include <cuda_bf16.h>
#include <cstdint>
#include <math.h>

#define T_TOK 4096
#define H_DIM 2048
#define F_DIM 1024
#define E_NUM 16
#define K_TOP 4

#if defined(__CUDA_ARCH__) && (defined(__CUDA_ARCH_FEAT_SM103_ALL) || \
    defined(__CUDA_ARCH_FEAT_SM100_ALL) || defined(__CUDA_ARCH_SPECIFIC__) || \
    defined(__CUDA_ARCH_FAMILY_SPECIFIC__))
#define HAS_TCGEN05 1
#else
#define HAS_TCGEN05 0
#endif

// idesc kind::f16: dtype=F32(1<<4), atype=BF16(1<<7), btype=BF16(1<<10), (N/8)<<17, (M/16)<<24
#define IDESC_128x128 0x08200490u

#define SM_TMEMPTR 0
#define SM_MBARM   8
#define SM_FULL0   16
#define SM_FULL1   24
#define SM_STAGE0  1024
// combined hi|lo tiles: 16KB = 128 rows x [64B hi | 64B lo], K=32 per tile
#define STAGE_BYTES (4 * 16384)      // gu: A0,A1,Wg,Wu   dn: A0,A1,Wd0,Wd1
#define MMA_SMEM (1024 + 2 * STAGE_BYTES)   // 132KB, depth-2 (depth>=3 hung: R14/R15/R16)

// packed tile addressing (combined hi|lo 16KB tiles, pre-swizzled SW128)
#define PA_TILE(e, mt, kc)  (((((size_t)(e) * 32 + (mt)) * 64) + (kc)) << 14)   // K=2048: 64 chunks
#define WGU_TILE(e, ft, kc) (((((size_t)(e) * 8  + (ft)) * 64) + (kc)) << 14)   // K=2048: 64 chunks
#define WD_TILE(e, ht, kc)  (((((size_t)(e) * 16 + (ht)) * 32) + (kc)) << 14)   // K=1024: 32 chunks
#define ACT_TILE(e, mt, kc) (((((size_t)(e) * 32 + (mt)) * 32) + (kc)) << 14)   // K=1024: 32 chunks

// ---------------- device scratch ---------------------------------------------------
__device__ int   d_cnt[E_NUM];
__device__ int   d_tok[E_NUM * T_TOK];
__device__ int   d_slot[T_TOK * K_TOP];
__device__ float d_wk[T_TOK * K_TOP];
__device__ __align__(128) char d_pa  [(size_t)E_NUM * T_TOK * H_DIM * 4];
__device__ __align__(128) char d_wgp [(size_t)E_NUM * F_DIM * H_DIM * 4];
__device__ __align__(128) char d_wup [(size_t)E_NUM * F_DIM * H_DIM * 4];
__device__ __align__(128) char d_wdp [(size_t)E_NUM * H_DIM * F_DIM * 4];
__device__ __align__(128) char d_actp[(size_t)E_NUM * T_TOK * F_DIM * 4];
__device__ float d_act_f32[(size_t)E_NUM * T_TOK * F_DIM];   // SIMT fallback path
__device__ float d_ybuf[(size_t)E_NUM * T_TOK * H_DIM];
__device__ float d_logits_fallback[(size_t)T_TOK * E_NUM];

// ---------------- portable PTX helpers ----------------------------------------------
__device__ __forceinline__ uint32_t elect_one_pred() {
    uint32_t pred;
    asm volatile("{\n\t.reg .pred p;\n\telect.sync _|p, 0xFFFFFFFF;\n\t"
                 "selp.b32 %0, 1, 0, p;\n\t}" : "=r"(pred));
    return pred;
}
__device__ __forceinline__ uint32_t smem_to_u32(const void* p) {
    uint32_t a;
    asm("{ .reg .u64 t; cvta.to.shared.u64 t, %1; cvt.u32.u64 %0, t; }" : "=r"(a) : "l"(p));
    return a;
}
__device__ __forceinline__ uint32_t swz(uint32_t off) { return off ^ ((off >> 3) & 0x70); }

#define MBARRIER_INIT(mbar, count) \
    asm volatile("mbarrier.init.shared.b64 [%0], %1;" :: "r"((uint32_t)(mbar)), "r"((uint32_t)(count)) : "memory")
#define MBARRIER_INVAL(mbar) \
    asm volatile("mbarrier.inval.shared.b64 [%0];" :: "r"((uint32_t)(mbar)) : "memory")
#define MBARRIER_EXPECT_TX(mbar, bytes) \
    asm volatile("mbarrier.arrive.expect_tx.shared.b64 _, [%0], %1;" :: "r"((uint32_t)(mbar)), "r"((uint32_t)(bytes)) : "memory")

#define MBARRIER_WAIT_PARITY(mbar_smem_addr, phase_parity) do { \
    uint32_t _mbar = (uint32_t)(mbar_smem_addr); \
    uint32_t _parity = (uint32_t)(phase_parity); \
    uint32_t _done; \
    asm volatile("{\n\t.reg .pred p;\n\t" \
        "mbarrier.try_wait.parity.acquire.cta.shared::cta.b64 p, [%1], %2;\n\t" \
        "selp.b32 %0, 1, 0, p;\n\t}" \
        : "=r"(_done) : "r"(_mbar), "r"(_parity) : "memory"); \
    if (!_done) { \
        asm volatile("{\n\t.reg .pred P1;\n\t" \
            "WAIT_LOOP_%=:\n\t" \
            "mbarrier.try_wait.parity.acquire.cta.shared::cta.b64 P1, [%0], %1, 0x989680;\n\t" \
            "@P1 bra.uni WAIT_DONE_%=;\n\t" \
            "bra.uni WAIT_LOOP_%=;\n\t" \
            "WAIT_DONE_%=:\n\t}" \
            :: "r"(_mbar), "r"(_parity) : "memory"); \
    } \
} while (0)

__device__ __forceinline__ uint32_t pack_bf16x2_hi(float f0, float f1) {
    __nv_bfloat162 h = __floats2bfloat162_rn(f0, f1);
    return *(uint32_t*)&h;
}
__device__ __forceinline__ uint32_t pack_bf16x2_lo(float f0, float f1) {
    __nv_bfloat16 h0 = __float2bfloat16(f0), h1 = __float2bfloat16(f1);
    __nv_bfloat162 l = __floats2bfloat162_rn(f0 - __bfloat162float(h0),
                                             f1 - __bfloat162float(h1));
    return *(uint32_t*)&l;
}

#if HAS_TCGEN05
#define TCGEN05_ALLOC(smem_addr, nCols) \
    asm volatile("tcgen05.alloc.cta_group::1.sync.aligned.shared::cta.b32 [%0], %1;" \
                 :: "r"((uint32_t)(smem_addr)), "r"((uint32_t)(nCols)) : "memory")
#define TCGEN05_RELINQ() \
    asm volatile("tcgen05.relinquish_alloc_permit.cta_group::1.sync.aligned;")
#define TCGEN05_DEALLOC(tmem, nCols) \
    asm volatile("tcgen05.dealloc.cta_group::1.sync.aligned.b32 %0, %1;" :: "r"(tmem), "r"((uint32_t)(nCols)))
#define TCGEN05_COMMIT(mbar) \
    asm volatile("tcgen05.commit.cta_group::1.mbarrier::arrive::one.shared::cluster.b64 [%0];" \
                 :: "r"((uint32_t)(mbar)) : "memory")
#define TCGEN05_FENCE_AFTER() asm volatile("tcgen05.fence::after_thread_sync;" ::: "memory")
#define TCGEN05_WAIT_LD()     asm volatile("tcgen05.wait::ld.sync.aligned;" ::: "memory")

#define TCGEN05_LD_32X32B_X32(r, tmem_addr) \
    asm volatile("tcgen05.ld.sync.aligned.32x32b.x32.b32 " \
        "{%0, %1, %2, %3, %4, %5, %6, %7, %8, %9, %10, %11, %12, %13, %14, %15, " \
        " %16, %17, %18, %19, %20, %21, %22, %23, %24, %25, %26, %27, %28, %29, %30, %31}, [%32];" \
        : "=r"((r)[0]),  "=r"((r)[1]),  "=r"((r)[2]),  "=r"((r)[3]), \
          "=r"((r)[4]),  "=r"((r)[5]),  "=r"((r)[6]),  "=r"((r)[7]), \
          "=r"((r)[8]),  "=r"((r)[9]),  "=r"((r)[10]), "=r"((r)[11]), \
          "=r"((r)[12]), "=r"((r)[13]), "=r"((r)[14]), "=r"((r)[15]), \
          "=r"((r)[16]), "=r"((r)[17]), "=r"((r)[18]), "=r"((r)[19]), \
          "=r"((r)[20]), "=r"((r)[21]), "=r"((r)[22]), "=r"((r)[23]), \
          "=r"((r)[24]), "=r"((r)[25]), "=r"((r)[26]), "=r"((r)[27]), \
          "=r"((r)[28]), "=r"((r)[29]), "=r"((r)[30]), "=r"((r)[31]) \
        : "r"(tmem_addr))

static constexpr uint64_t SMEM_DESC_BASE_SW128 =
    (uint64_t(2) << 61) | (uint64_t(1) << 46) | (uint64_t(64) << 32) | (uint64_t(1) << 16);
#define MAKE_SMEM_DESC(base_addr) (SMEM_DESC_BASE_SW128 | ((uint64_t)((base_addr) >> 4) & 0x3FFF))

__device__ __forceinline__ void mma_f16_ss(uint32_t d, uint64_t a, uint64_t b, bool acc) {
    uint32_t en = acc ? 1u : 0u;
    asm volatile("{\n\t.reg .pred p;\n\tsetp.ne.u32 p, %5, 0;\n\t"
                 "tcgen05.mma.cta_group::1.kind::f16 [%0], %1, %2, %3, {%4, %4, %4, %4}, p;\n\t}"
                 :: "r"(d), "l"(a), "l"(b), "r"(IDESC_128x128), "r"(0u), "r"(en) : "memory");
}

__device__ __forceinline__ void bulk_cp(uint32_t dst, const void* src, uint32_t bytes, uint32_t mbar) {
    asm volatile("cp.async.bulk.shared::cluster.global.mbarrier::complete_tx::bytes "
                 "[%0], [%1], %2, [%3];"
                 :: "r"(dst), "l"(src), "r"(bytes), "r"(mbar) : "memory");
}
#endif  // HAS_TCGEN05

// ---------------- init ---------------------------------------------------------------
__global__ void init_kernel() {
    if (threadIdx.x < E_NUM) d_cnt[threadIdx.x] = 0;
}

// ---------------- router (validated) ---------------------------------------------------
__global__ void __launch_bounds__(256) router_kernel(const float* __restrict__ x,
                                                     const float* __restrict__ wg,
                                                     float* __restrict__ logits_out) {
    int t = blockIdx.x, tid = threadIdx.x;
    float acc[E_NUM];
#pragma unroll
    for (int e = 0; e < E_NUM; e++) acc[e] = 0.f;
    const float* xr = x + (size_t)t * H_DIM;
    for (int h = tid; h < H_DIM; h += 256) {
        float xv = xr[h];
        const float* wrow = wg + (size_t)h * E_NUM;
#pragma unroll
        for (int e = 0; e < E_NUM; e++) acc[e] += xv * wrow[e];
    }
#pragma unroll
    for (int e = 0; e < E_NUM; e++) {
#pragma unroll
        for (int o = 16; o > 0; o >>= 1)
            acc[e] += __shfl_down_sync(0xffffffffu, acc[e], o);
    }
    __shared__ float sred[8][E_NUM];
    __shared__ float logits[E_NUM];
    int warp = tid >> 5, lane = tid & 31;
    if (lane == 0) {
#pragma unroll
        for (int e = 0; e < E_NUM; e++) sred[warp][e] = acc[e];
    }
    __syncthreads();
    if (tid < E_NUM) {
        float v = 0.f;
#pragma unroll
        for (int w = 0; w < 8; w++) v += sred[w][tid];
        logits[tid] = v;
        logits_out[(size_t)t * E_NUM + tid] = v;
    }
    __syncthreads();
    if (tid == 0) {
        float l[E_NUM];
#pragma unroll
        for (int e = 0; e < E_NUM; e++) l[e] = logits[e];
        int sel[K_TOP]; float selv[K_TOP]; bool used[E_NUM];
#pragma unroll
        for (int e = 0; e < E_NUM; e++) used[e] = false;
#pragma unroll
        for (int k = 0; k < K_TOP; k++) {
            int best = -1; float bv = -1e30f;
            for (int e = 0; e < E_NUM; e++)
                if (!used[e] && l[e] > bv) { bv = l[e]; best = e; }
            used[best] = true; sel[k] = best; selv[k] = bv;
        }
        float m = selv[0], w[K_TOP], sum = 0.f;
#pragma unroll
        for (int k = 0; k < K_TOP; k++) { w[k] = expf(selv[k] - m); sum += w[k]; }
        float inv = 1.f / sum;
#pragma unroll
        for (int k = 0; k < K_TOP; k++) {
            int e = sel[k];
            int pos = atomicAdd(&d_cnt[e], 1);
            d_tok[e * T_TOK + pos] = t;
            d_slot[t * K_TOP + k] = e * T_TOK + pos;
            d_wk[t * K_TOP + k] = w[k] * inv;
        }
    }
}

// ---------------- pack gathered A rows into combined hi|lo tiles (validated) ----------
__global__ void __launch_bounds__(256) pack_a_kernel(const float* __restrict__ x) {
#if HAS_TCGEN05
    int mt = blockIdx.x, e = blockIdx.y;
    int n = d_cnt[e];
    if (mt * 128 >= n) return;
    int tid = threadIdx.x;
    int row = tid >> 1, half = tid & 1;
    int r = mt * 128 + row;
    int t = (r < n) ? d_tok[e * T_TOK + r] : -1;
    const float* xr = (t >= 0) ? (x + (size_t)t * H_DIM) : nullptr;

    for (int kc = 0; kc < 64; kc++) {
        float f[16];
        if (xr) {
#pragma unroll
            for (int j = 0; j < 4; j++)
                *(float4*)&f[j * 4] = *(const float4*)(xr + kc * 32 + half * 16 + j * 4);
        } else {
#pragma unroll
            for (int j = 0; j < 16; j++) f[j] = 0.f;
        }
        uint32_t hi[8], lo[8];
#pragma unroll
        for (int m = 0; m < 8; m++) {
            hi[m] = pack_bf16x2_hi(f[2 * m], f[2 * m + 1]);
            lo[m] = pack_bf16x2_lo(f[2 * m], f[2 * m + 1]);
        }
        size_t tb = PA_TILE(e, mt, kc);
#pragma unroll
        for (int q = 0; q < 2; q++) {
            uint32_t offh = swz((uint32_t)row * 128 + half * 32 + q * 16);
            uint32_t offl = swz((uint32_t)row * 128 + 64 + half * 32 + q * 16);
            *(uint4*)(d_pa + tb + offh) = ((uint4*)hi)[q];
            *(uint4*)(d_pa + tb + offl) = ((uint4*)lo)[q];
        }
    }
#endif
}

// ---------------- pack weights (validated in R12/R13) ----------------------------------
__global__ void __launch_bounds__(256) pack_w2_kernel(
    const float* __restrict__ srcA, char* __restrict__ dA,
    const float* __restrict__ srcB, char* __restrict__ dB,
    int inner) {
#if HAS_TCGEN05
    int nt = blockIdx.x, kb = blockIdx.y;
    int e = blockIdx.z & 15, which = blockIdx.z >> 4;
    int KB = gridDim.y;
    const float* s = (which ? srcB : srcA) + (size_t)e * (KB * 64) * inner;
    char* d = which ? dB : dA;

    __shared__ float tile[64][129];
    int tid = threadIdx.x;
    for (int idx = tid; idx < 8192; idx += 256) {
        int k = idx >> 7, nn = idx & 127;
        tile[k][nn] = s[(size_t)(kb * 64 + k) * inner + nt * 128 + nn];
    }
    __syncthreads();
    size_t tb = ((((size_t)e * gridDim.x + nt) * (2 * KB)) + 2 * kb) << 14;
#pragma unroll
    for (int gi = 0; gi < 8; gi++) {
        int g = tid + gi * 256;
        int t2 = g >> 10;
        int g1 = g & 1023;
        int nn = g1 >> 3, q8 = g1 & 7;
        bool ishi = q8 < 4;
        int q = q8 & 3;
        uint32_t v[4];
#pragma unroll
        for (int m = 0; m < 4; m++) {
            float f0 = tile[t2 * 32 + q * 8 + 2 * m][nn];
            float f1 = tile[t2 * 32 + q * 8 + 2 * m + 1][nn];
            v[m] = ishi ? pack_bf16x2_hi(f0, f1) : pack_bf16x2_lo(f0, f1);
        }
        uint32_t off = swz((uint32_t)nn * 128 + (ishi ? q * 16 : 64 + q * 16));
        *(uint4*)(d + tb + ((size_t)t2 << 14) + off) = *(uint4*)v;
    }
#endif
}

// ================= tcgen05 MMA kernels (R13-validated, depth-2) =======================
// gu: M=256 (two M-tiles), N=128. TMEM: M0g@0, M0u@128, M1g@256, M1u@384.
__global__ void __launch_bounds__(256, 1) gu_mma_kernel() {
#if HAS_TCGEN05
    int e = blockIdx.z;
    int n = d_cnt[e];
    int mt0 = blockIdx.x * 2;
    if (mt0 * 128 >= n) return;
    int ft = blockIdx.y;

    extern __shared__ char dyn_smem[];
    uint32_t sb = smem_to_u32(dyn_smem);
    int tid = threadIdx.x, wid = tid >> 5;

    if (wid == 0) TCGEN05_ALLOC(sb + SM_TMEMPTR, 512);
    if (tid == 0) {
        MBARRIER_INIT(sb + SM_MBARM, 1);
        MBARRIER_INIT(sb + SM_FULL0, 1);
        MBARRIER_INIT(sb + SM_FULL1, 1);
    }
    __syncthreads();
    uint32_t tmem;
    asm volatile("ld.shared.b32 %0, [%1];" : "=r"(tmem) : "r"(sb + SM_TMEMPTR));

    const char* pa0 = d_pa  + PA_TILE(e, mt0,     0);
    const char* pa1 = d_pa  + PA_TILE(e, mt0 + 1, 0);
    const char* wg  = d_wgp + WGU_TILE(e, ft, 0);
    const char* wu  = d_wup + WGU_TILE(e, ft, 0);

    const int NC = 64;
    auto load_chunk = [&](int buf, int kc) {
        uint32_t st = sb + SM_STAGE0 + buf * STAGE_BYTES;
        uint32_t fb = sb + (buf ? SM_FULL1 : SM_FULL0);
        MBARRIER_EXPECT_TX(fb, STAGE_BYTES);
        size_t o = (size_t)kc << 14;
        bulk_cp(st + 0 * 16384, pa0 + o, 16384, fb);
        bulk_cp(st + 1 * 16384, pa1 + o, 16384, fb);
        bulk_cp(st + 2 * 16384, wg + o, 16384, fb);
        bulk_cp(st + 3 * 16384, wu + o, 16384, fb);
    };

    if (tid == 0) { load_chunk(0, 0); load_chunk(1, 1); }

    for (int i = 0; i < NC; i++) {
        int buf = i & 1;
        MBARRIER_WAIT_PARITY(sb + (buf ? SM_FULL1 : SM_FULL0), (i >> 1) & 1);

        if (wid == 0 && elect_one_pred()) {
            uint32_t st = sb + SM_STAGE0 + buf * STAGE_BYTES;
            uint64_t a0 = MAKE_SMEM_DESC(st + 0 * 16384);
            uint64_t a1 = MAKE_SMEM_DESC(st + 1 * 16384);
            uint64_t g  = MAKE_SMEM_DESC(st + 2 * 16384);
            uint64_t u  = MAKE_SMEM_DESC(st + 3 * 16384);
#pragma unroll
            for (int k = 0; k < 2; k++) {
                uint64_t o = (uint64_t)k * 2;
                uint64_t ol = o + 4;
                bool acc = !(i == 0 && k == 0);
                mma_f16_ss(tmem + 0,   a0 + o,  g + o,  acc);
                mma_f16_ss(tmem + 0,   a0 + o,  g + ol, true);
                mma_f16_ss(tmem + 0,   a0 + ol, g + o,  true);
                mma_f16_ss(tmem + 128, a0 + o,  u + o,  acc);
                mma_f16_ss(tmem + 128, a0 + o,  u + ol, true);
                mma_f16_ss(tmem + 128, a0 + ol, u + o,  true);
                mma_f16_ss(tmem + 256, a1 + o,  g + o,  acc);
                mma_f16_ss(tmem + 256, a1 + o,  g + ol, true);
                mma_f16_ss(tmem + 256, a1 + ol, g + o,  true);
                mma_f16_ss(tmem + 384, a1 + o,  u + o,  acc);
                mma_f16_ss(tmem + 384, a1 + o,  u + ol, true);
                mma_f16_ss(tmem + 384, a1 + ol, u + o,  true);
            }
            TCGEN05_COMMIT(sb + SM_MBARM);
        }
        // tid0 observes MBARM phases strictly in order -> no parity aliasing.
        if (tid == 0 && i + 2 < NC) {
            MBARRIER_WAIT_PARITY(sb + SM_MBARM, i & 1);
            load_chunk(buf, i + 2);
        }
    }

    if (tid == 0) {
        MBARRIER_WAIT_PARITY(sb + SM_MBARM, (NC - 2) & 1);
        MBARRIER_WAIT_PARITY(sb + SM_MBARM, (NC - 1) & 1);
    }
    __syncthreads();
    TCGEN05_FENCE_AFTER();

    if (wid < 4) {
        int lane = tid & 31;
        int lrow = wid * 32 + lane;
        uint32_t rg[32], ru[32];
#pragma unroll
        for (int half = 0; half < 2; half++) {
#pragma unroll
            for (int cb = 0; cb < 4; cb++) {
                TCGEN05_LD_32X32B_X32(rg, tmem + half * 256 + cb * 32);
                TCGEN05_LD_32X32B_X32(ru, tmem + half * 256 + 128 + cb * 32);
                TCGEN05_WAIT_LD();
                uint32_t phi[16], plo[16];
#pragma unroll
                for (int j = 0; j < 16; j++) {
                    float g0 = __uint_as_float(rg[2 * j]);
                    float g1 = __uint_as_float(rg[2 * j + 1]);
                    float u0 = __uint_as_float(ru[2 * j]);
                    float u1 = __uint_as_float(ru[2 * j + 1]);
                    float a0 = g0 / (1.f + __expf(-g0)) * u0;
                    float a1 = g1 / (1.f + __expf(-g1)) * u1;
                    phi[j] = pack_bf16x2_hi(a0, a1);
                    plo[j] = pack_bf16x2_lo(a0, a1);
                }
                int kc = ft * 4 + cb;
                size_t tb = ACT_TILE(e, mt0 + half, kc);
#pragma unroll
                for (int q = 0; q < 4; q++) {
                    uint32_t offh = swz((uint32_t)lrow * 128 + q * 16);
                    uint32_t offl = swz((uint32_t)lrow * 128 + 64 + q * 16);
                    *(uint4*)(d_actp + tb + offh) = ((uint4*)phi)[q];
                    *(uint4*)(d_actp + tb + offl) = ((uint4*)plo)[q];
                }
            }
        }
    }
    __syncthreads();
    if (tid == 0) {
        MBARRIER_INVAL(sb + SM_MBARM);
        MBARRIER_INVAL(sb + SM_FULL0);
        MBARRIER_INVAL(sb + SM_FULL1);
    }
    __syncthreads();
    if (wid == 0) {
        TCGEN05_RELINQ();
        TCGEN05_DEALLOC(tmem, 512);
    }
#endif
}

// dn: M=256, N=256. TMEM: M0N0@0, M0N1@128, M1N0@256, M1N1@384.
__global__ void __launch_bounds__(256, 1) dn_mma_kernel() {
#if HAS_TCGEN05
    int e = blockIdx.z;
    int n = d_cnt[e];
    int mt0 = blockIdx.x * 2;
    if (mt0 * 128 >= n) return;
    int ht0 = blockIdx.y * 2;

    extern __shared__ char dyn_smem[];
    uint32_t sb = smem_to_u32(dyn_smem);
    int tid = threadIdx.x, wid = tid >> 5;

    if (wid == 0) TCGEN05_ALLOC(sb + SM_TMEMPTR, 512);
    if (tid == 0) {
        MBARRIER_INIT(sb + SM_MBARM, 1);
        MBARRIER_INIT(sb + SM_FULL0, 1);
        MBARRIER_INIT(sb + SM_FULL1, 1);
    }
    __syncthreads();
    uint32_t tmem;
    asm volatile("ld.shared.b32 %0, [%1];" : "=r"(tmem) : "r"(sb + SM_TMEMPTR));

    const char* a0 = d_actp + ACT_TILE(e, mt0,     0);
    const char* a1 = d_actp + ACT_TILE(e, mt0 + 1, 0);
    const char* w0 = d_wdp  + WD_TILE(e, ht0,     0);
    const char* w1 = d_wdp  + WD_TILE(e, ht0 + 1, 0);

    const int NC = 32;
    auto load_chunk = [&](int buf, int kc) {
        uint32_t st = sb + SM_STAGE0 + buf * STAGE_BYTES;
        uint32_t fb = sb + (buf ? SM_FULL1 : SM_FULL0);
        MBARRIER_EXPECT_TX(fb, STAGE_BYTES);
        size_t o = (size_t)kc << 14;
        bulk_cp(st + 0 * 16384, a0 + o, 16384, fb);
        bulk_cp(st + 1 * 16384, a1 + o, 16384, fb);
        bulk_cp(st + 2 * 16384, w0 + o, 16384, fb);
        bulk_cp(st + 3 * 16384, w1 + o, 16384, fb);
    };

    if (tid == 0) { load_chunk(0, 0); load_chunk(1, 1); }

    for (int i = 0; i < NC; i++) {
        int buf = i & 1;
        MBARRIER_WAIT_PARITY(sb + (buf ? SM_FULL1 : SM_FULL0), (i >> 1) & 1);

        if (wid == 0 && elect_one_pred()) {
            uint32_t st = sb + SM_STAGE0 + buf * STAGE_BYTES;
            uint64_t da0 = MAKE_SMEM_DESC(st + 0 * 16384);
            uint64_t da1 = MAKE_SMEM_DESC(st + 1 * 16384);
            uint64_t db0 = MAKE_SMEM_DESC(st + 2 * 16384);
            uint64_t db1 = MAKE_SMEM_DESC(st + 3 * 16384);
#pragma unroll
            for (int k = 0; k < 2; k++) {
                uint64_t o = (uint64_t)k * 2;
                uint64_t ol = o + 4;
                bool acc = !(i == 0 && k == 0);
                mma_f16_ss(tmem + 0,   da0 + o,  db0 + o,  acc);
                mma_f16_ss(tmem + 0,   da0 + o,  db0 + ol, true);
                mma_f16_ss(tmem + 0,   da0 + ol, db0 + o,  true);
                mma_f16_ss(tmem + 128, da0 + o,  db1 + o,  acc);
                mma_f16_ss(tmem + 128, da0 + o,  db1 + ol, true);
                mma_f16_ss(tmem + 128, da0 + ol, db1 + o,  true);
                mma_f16_ss(tmem + 256, da1 + o,  db0 + o,  acc);
                mma_f16_ss(tmem + 256, da1 + o,  db0 + ol, true);
                mma_f16_ss(tmem + 256, da1 + ol, db0 + o,  true);
                mma_f16_ss(tmem + 384, da1 + o,  db1 + o,  acc);
                mma_f16_ss(tmem + 384, da1 + o,  db1 + ol, true);
                mma_f16_ss(tmem + 384, da1 + ol, db1 + o,  true);
            }
            TCGEN05_COMMIT(sb + SM_MBARM);
        }
        if (tid == 0 && i + 2 < NC) {
            MBARRIER_WAIT_PARITY(sb + SM_MBARM, i & 1);
            load_chunk(buf, i + 2);
        }
    }

    if (tid == 0) {
        MBARRIER_WAIT_PARITY(sb + SM_MBARM, (NC - 2) & 1);
        MBARRIER_WAIT_PARITY(sb + SM_MBARM, (NC - 1) & 1);
    }
    __syncthreads();
    TCGEN05_FENCE_AFTER();

    if (wid < 4) {
        int lane = tid & 31;
        uint32_t r[32];
#pragma unroll
        for (int mh = 0; mh < 2; mh++) {
            size_t rowidx = (size_t)e * T_TOK + (mt0 + mh) * 128 + wid * 32 + lane;
#pragma unroll
            for (int nh = 0; nh < 2; nh++) {
                int col0 = (ht0 + nh) * 128;
#pragma unroll
                for (int cb = 0; cb < 4; cb++) {
                    TCGEN05_LD_32X32B_X32(r, tmem + mh * 256 + nh * 128 + cb * 32);
                    TCGEN05_WAIT_LD();
                    uint4* dst = (uint4*)(d_ybuf + rowidx * H_DIM + col0 + cb * 32);
#pragma unroll
                    for (int q = 0; q < 8; q++) dst[q] = ((uint4*)r)[q];
                }
            }
        }
    }
    __syncthreads();
    if (tid == 0) {
        MBARRIER_INVAL(sb + SM_MBARM);
        MBARRIER_INVAL(sb + SM_FULL0);
        MBARRIER_INVAL(sb + SM_FULL1);
    }
    __syncthreads();
    if (wid == 0) {
        TCGEN05_RELINQ();
        TCGEN05_DEALLOC(tmem, 512);
    }
#endif
}

// ================= SIMT fallback path (validated; empty under tcgen05 build) ===========
__global__ void __launch_bounds__(256) gateup_simt_kernel(const float* __restrict__ x,
                                                          const float* __restrict__ Wg,
                                                          const float* __restrict__ Wu) {
#if !HAS_TCGEN05
    int e = blockIdx.z;
    int n = d_cnt[e];
    int row0 = blockIdx.x * 64;
    if (row0 >= n) return;
    int col0 = blockIdx.y * 64;

    __shared__ float Xs[64][17];
    __shared__ float Gs[16][64];
    __shared__ float Us[16][64];
    __shared__ int   toks[64];

    int tid = threadIdx.x;
    if (tid < 64) {
        int r = row0 + tid;
        toks[tid] = (r < n) ? d_tok[e * T_TOK + r] : -1;
    }
    __syncthreads();

    const float* wgp = Wg + (size_t)e * H_DIM * F_DIM;
    const float* wup = Wu + (size_t)e * H_DIM * F_DIM;

    float acc1[4][4], acc2[4][4];
#pragma unroll
    for (int i = 0; i < 4; i++)
#pragma unroll
        for (int j = 0; j < 4; j++) { acc1[i][j] = 0.f; acc2[i][j] = 0.f; }

    int tx = tid & 15, ty = tid >> 4;
    int xr = tid >> 2, xk = (tid & 3) * 4;
    int br = tid >> 4, bc = (tid & 15) * 4;

    int tk = toks[xr];
    const float* xrow = (tk >= 0) ? (x + (size_t)tk * H_DIM) : nullptr;

    for (int k0 = 0; k0 < H_DIM; k0 += 16) {
        float4 xv = make_float4(0.f, 0.f, 0.f, 0.f);
        if (xrow) xv = *(const float4*)(xrow + k0 + xk);
        Xs[xr][xk + 0] = xv.x; Xs[xr][xk + 1] = xv.y;
        Xs[xr][xk + 2] = xv.z; Xs[xr][xk + 3] = xv.w;

        *(float4*)&Gs[br][bc] = *(const float4*)(wgp + (size_t)(k0 + br) * F_DIM + col0 + bc);
        *(float4*)&Us[br][bc] = *(const float4*)(wup + (size_t)(k0 + br) * F_DIM + col0 + bc);
        __syncthreads();

#pragma unroll
        for (int kk = 0; kk < 16; kk++) {
            float a0 = Xs[ty * 4 + 0][kk];
            float a1 = Xs[ty * 4 + 1][kk];
            float a2 = Xs[ty * 4 + 2][kk];
            float a3 = Xs[ty * 4 + 3][kk];
            float4 bg = *(float4*)&Gs[kk][tx * 4];
            float4 bu = *(float4*)&Us[kk][tx * 4];

            acc1[0][0] += a0 * bg.x; acc1[0][1] += a0 * bg.y; acc1[0][2] += a0 * bg.z; acc1[0][3] += a0 * bg.w;
            acc1[1][0] += a1 * bg.x; acc1[1][1] += a1 * bg.y; acc1[1][2] += a1 * bg.z; acc1[1][3] += a1 * bg.w;
            acc1[2][0] += a2 * bg.x; acc1[2][1] += a2 * bg.y; acc1[2][2] += a2 * bg.z; acc1[2][3] += a2 * bg.w;
            acc1[3][0] += a3 * bg.x; acc1[3][1] += a3 * bg.y; acc1[3][2] += a3 * bg.z; acc1[3][3] += a3 * bg.w;

            acc2[0][0] += a0 * bu.x; acc2[0][1] += a0 * bu.y; acc2[0][2] += a0 * bu.z; acc2[0][3] += a0 * bu.w;
            acc2[1][0] += a1 * bu.x; acc2[1][1] += a1 * bu.y; acc2[1][2] += a1 * bu.z; acc2[1][3] += a1 * bu.w;
            acc2[2][0] += a2 * bu.x; acc2[2][1] += a2 * bu.y; acc2[2][2] += a2 * bu.z; acc2[2][3] += a2 * bu.w;
            acc2[3][0] += a3 * bu.x; acc2[3][1] += a3 * bu.y; acc2[3][2] += a3 * bu.z; acc2[3][3] += a3 * bu.w;
        }
        __syncthreads();
    }

#pragma unroll
    for (int i = 0; i < 4; i++) {
        int r = row0 + ty * 4 + i;
        if (r < n) {
            float* dst = d_act_f32 + ((size_t)e * T_TOK + r) * F_DIM + col0 + tx * 4;
#pragma unroll
            for (int j = 0; j < 4; j++) {
                float g = acc1[i][j];
                float s = g / (1.f + expf(-g));
                dst[j] = s * acc2[i][j];
            }
        }
    }
#endif
}

__global__ void __launch_bounds__(256) down_simt_kernel(const float* __restrict__ Wd) {
#if !HAS_TCGEN05
    int e = blockIdx.z;
    int n = d_cnt[e];
    int row0 = blockIdx.x * 64;
    if (row0 >= n) return;
    int col0 = blockIdx.y * 64;

    __shared__ float Xs[64][17];
    __shared__ float Bs[16][64];

    int tid = threadIdx.x;
    int tx = tid & 15, ty = tid >> 4;
    int xr = tid >> 2, xk = (tid & 3) * 4;
    int br = tid >> 4, bc = (tid & 15) * 4;

    const float* wdp = Wd + (size_t)e * F_DIM * H_DIM;
    const float* arow = (row0 + xr < n)
        ? (d_act_f32 + ((size_t)e * T_TOK + row0 + xr) * F_DIM) : nullptr;

    float acc[4][4];
#pragma unroll
    for (int i = 0; i < 4; i++)
#pragma unroll
        for (int j = 0; j < 4; j++) acc[i][j] = 0.f;

    for (int k0 = 0; k0 < F_DIM; k0 += 16) {
        float4 xv = make_float4(0.f, 0.f, 0.f, 0.f);
        if (arow) xv = *(const float4*)(arow + k0 + xk);
        Xs[xr][xk + 0] = xv.x; Xs[xr][xk + 1] = xv.y;
        Xs[xr][xk + 2] = xv.z; Xs[xr][xk + 3] = xv.w;

        *(float4*)&Bs[br][bc] = *(const float4*)(wdp + (size_t)(k0 + br) * H_DIM + col0 + bc);
        __syncthreads();

#pragma unroll
        for (int kk = 0; kk < 16; kk++) {
            float a0 = Xs[ty * 4 + 0][kk];
            float a1 = Xs[ty * 4 + 1][kk];
            float a2 = Xs[ty * 4 + 2][kk];
            float a3 = Xs[ty * 4 + 3][kk];
            float4 b = *(float4*)&Bs[kk][tx * 4];

            acc[0][0] += a0 * b.x; acc[0][1] += a0 * b.y; acc[0][2] += a0 * b.z; acc[0][3] += a0 * b.w;
            acc[1][0] += a1 * b.x; acc[1][1] += a1 * b.y; acc[1][2] += a1 * b.z; acc[1][3] += a1 * b.w;
            acc[2][0] += a2 * b.x; acc[2][1] += a2 * b.y; acc[2][2] += a2 * b.z; acc[2][3] += a2 * b.w;
            acc[3][0] += a3 * b.x; acc[3][1] += a3 * b.y; acc[3][2] += a3 * b.z; acc[3][3] += a3 * b.w;
        }
        __syncthreads();
    }

#pragma unroll
    for (int i = 0; i < 4; i++) {
        int r = row0 + ty * 4 + i;
        if (r < n) {
            float* dst = d_ybuf + ((size_t)e * T_TOK + r) * H_DIM + col0 + tx * 4;
#pragma unroll
            for (int j = 0; j < 4; j++) dst[j] = acc[i][j];
        }
    }
#endif
}

// ---------------- combine -----------------------------------------------------------
__global__ void __launch_bounds__(256) combine_kernel(float* __restrict__ out) {
    int t = blockIdx.x, tid = threadIdx.x;
    __shared__ int sl[K_TOP];
    __shared__ float sw[K_TOP];
    if (tid < K_TOP) {
        sl[tid] = d_slot[t * K_TOP + tid];
        sw[tid] = d_wk[t * K_TOP + tid];
    }
    __syncthreads();
    const float* y0 = d_ybuf + (size_t)sl[0] * H_DIM;
    const float* y1 = d_ybuf + (size_t)sl[1] * H_DIM;
    const float* y2 = d_ybuf + (size_t)sl[2] * H_DIM;
    const float* y3 = d_ybuf + (size_t)sl[3] * H_DIM;
    float w0 = sw[0], w1 = sw[1], w2 = sw[2], w3 = sw[3];
    float* op = out + (size_t)t * H_DIM;
    for (int h = tid * 4; h < H_DIM; h += 256 * 4) {
        float4 a = *(const float4*)(y0 + h);
        float4 b = *(const float4*)(y1 + h);
        float4 c = *(const float4*)(y2 + h);
        float4 d = *(const float4*)(y3 + h);
        float4 r;
        r.x = w0 * a.x + w1 * b.x + w2 * c.x + w3 * d.x;
        r.y = w0 * a.y + w1 * b.y + w2 * c.y + w3 * d.y;
        r.z = w0 * a.z + w1 * b.z + w2 * c.z + w3 * d.z;
        r.w = w0 * a.w + w1 * b.w + w2 * c.w + w3 * d.w;
        *(float4*)(op + h) = r;
    }
}

// ---------------- launch: stream fork/join to overlap weight packs ----------------------
extern "C" void kernel_launch(void* const* d_in, const int* in_sizes, int n_in,
                              void* d_out, int out_size) {
    const float* x     = (const float*)d_in[0];
    const float* wgate = (const float*)d_in[1];
    const float* Wg    = (const float*)d_in[2];
    const float* Wu    = (const float*)d_in[3];
    const float* Wd    = (const float*)d_in[4];
    float* out = (float*)d_out;

    float* logits_out;
    if (out_size >= T_TOK * H_DIM + T_TOK * E_NUM) {
        logits_out = out + (size_t)T_TOK * H_DIM;
    } else {
        static float* fb = nullptr;
        if (!fb) cudaGetSymbolAddress((void**)&fb, d_logits_fallback);
        logits_out = fb;
    }

    cudaFuncSetAttribute(gu_mma_kernel, cudaFuncAttributeMaxDynamicSharedMemorySize, MMA_SMEM);
    cudaFuncSetAttribute(dn_mma_kernel, cudaFuncAttributeMaxDynamicSharedMemorySize, MMA_SMEM);

    char *wgp, *wup, *wdp;
    cudaGetSymbolAddress((void**)&wgp, d_wgp);
    cudaGetSymbolAddress((void**)&wup, d_wup);
    cudaGetSymbolAddress((void**)&wdp, d_wdp);

    // Side streams + events created ONCE on the first (non-capture) call; the capture
    // call reuses them via the documented event-fork/join pattern. No allocations or
    // sync calls during capture.
    static cudaStream_t s1 = nullptr, s2 = nullptr;
    static cudaEvent_t ev0 = nullptr, ev1 = nullptr, ev2 = nullptr;
    if (!s1) {
        cudaStreamCreateWithFlags(&s1, cudaStreamNonBlocking);
        cudaStreamCreateWithFlags(&s2, cudaStreamNonBlocking);
        cudaEventCreateWithFlags(&ev0, cudaEventDisableTiming);
        cudaEventCreateWithFlags(&ev1, cudaEventDisableTiming);
        cudaEventCreateWithFlags(&ev2, cudaEventDisableTiming);
    }

    // main stream: init -> router -> pack_a  (token-dependent chain)
    init_kernel<<<1, 32>>>();
    cudaEventRecord(ev0, 0);
    cudaStreamWaitEvent(s1, ev0, 0);
    cudaStreamWaitEvent(s2, ev0, 0);

    // s1: Wg+Wu pack (input-only); s2: Wd pack (input-only)
    pack_w2_kernel<<<dim3(F_DIM / 128, H_DIM / 64, 2 * E_NUM), 256, 0, s1>>>(
        Wg, wgp, Wu, wup, F_DIM);
    cudaEventRecord(ev1, s1);
    pack_w2_kernel<<<dim3(H_DIM / 128, F_DIM / 64, E_NUM), 256, 0, s2>>>(
        Wd, wdp, Wd, wdp, H_DIM);
    cudaEventRecord(ev2, s2);

    router_kernel<<<T_TOK, 256>>>(x, wgate, logits_out);
    pack_a_kernel<<<dim3(T_TOK / 128, E_NUM), 256>>>(x);

    cudaStreamWaitEvent(0, ev1, 0);   // gu needs Wg/Wu packs
    gu_mma_kernel<<<dim3(T_TOK / 256, F_DIM / 128, E_NUM), 256, MMA_SMEM>>>();
    cudaStreamWaitEvent(0, ev2, 0);   // dn needs Wd pack (hidden under gu)
    dn_mma_kernel<<<dim3(T_TOK / 256, H_DIM / 256, E_NUM), 256, MMA_SMEM>>>();

    // ---- SIMT fallback path (no-op under the sm_103a build) ----
    gateup_simt_kernel<<<dim3(T_TOK / 64, F_DIM / 64, E_NUM), 256>>>(x, Wg, Wu);
    down_simt_kernel<<<dim3(T_TOK / 64, H_DIM / 64, E_NUM), 256>>>(Wd);

    combine_kernel<<<T_TOK, 256>>>(out);
}